// round 8
// baseline (speedup 1.0000x reference)
#include <cuda_runtime.h>
#include <cuda_bf16.h>
#include <cstdint>

#define NN      10000
#define EE      30000
#define FEDGE   8
#define EMB     64
#define HID     16
#define NG      64
#define NCOL    1088   // 1024 P | 64 Q
#define QOFF    1024

// ---------------- scratch (device globals) --------------------------------
__device__ __align__(128) float g_h0[EE * HID];
__device__ __align__(128) float g_h1[EE * HID];
__device__ __align__(128) float g_PQ[(size_t)NN * NCOL];
__device__ __align__(128) float g_agg0[NN * EMB];
__device__ __align__(128) float g_agg1[NN * EMB];
__device__ __align__(128) float g_agg2[NN * EMB];
__device__ __align__(128) float g_xr0[NN * EMB];
__device__ __align__(128) float g_xr1[NN * EMB];
__device__ __align__(128) float g_xr2[NN * EMB];
__device__ __align__(128) float g_WT0[NCOL * 32];  // [c][i] P+Q, conv0
__device__ __align__(128) float g_WT1[NCOL * 64];  // [c][i] P+Q, convs 1&2
__device__ __align__(128) float g_RT0[64 * 32];    // [o][i] rootT
__device__ __align__(128) float g_RT1[64 * 64];
__device__ __align__(128) float g_RT2[64 * 64];
__device__ __align__(128) float g_pool[NG * EMB];
// CSR by src (rebuilt every replay from constant inputs)
__device__ __align__(128) int g_deg[NN];
__device__ __align__(128) int g_fill[NN];
__device__ __align__(128) int g_rowptr[NN + 1];
__device__ __align__(128) int g_edst[EE];
__device__ __align__(128) int g_eid[EE];

// ---------------- helpers --------------------------------------------------
__device__ __forceinline__ uint32_t smem_u32(const void* p) {
    uint32_t a;
    asm("{ .reg .u64 t; cvta.to.shared.u64 t, %1; cvt.u32.u64 %0, t; }" : "=r"(a) : "l"(p));
    return a;
}
__device__ __forceinline__ void ldmx4(uint32_t* r, uint32_t addr) {
    asm volatile("ldmatrix.sync.aligned.m8n8.x4.shared.b16 {%0,%1,%2,%3}, [%4];"
        : "=r"(r[0]), "=r"(r[1]), "=r"(r[2]), "=r"(r[3]) : "r"(addr));
}
__device__ __forceinline__ void mma_bf16(float* d, const uint32_t* a,
                                         uint32_t b0, uint32_t b1) {
    asm volatile("mma.sync.aligned.m16n8k16.row.col.f32.bf16.bf16.f32 "
        "{%0,%1,%2,%3}, {%4,%5,%6,%7}, {%8,%9}, {%0,%1,%2,%3};"
        : "+f"(d[0]), "+f"(d[1]), "+f"(d[2]), "+f"(d[3])
        : "r"(a[0]), "r"(a[1]), "r"(a[2]), "r"(a[3]), "r"(b0), "r"(b1));
}
__device__ __forceinline__ void split_pack(float fx, float fy,
                                           uint32_t& hi, uint32_t& lo) {
    __nv_bfloat16 hx = __float2bfloat16(fx), hy = __float2bfloat16(fy);
    hi = ((uint32_t)__bfloat16_as_ushort(hy) << 16) | __bfloat16_as_ushort(hx);
    __nv_bfloat16 lx = __float2bfloat16(fx - __bfloat162float(hx));
    __nv_bfloat16 ly = __float2bfloat16(fy - __bfloat162float(hy));
    lo = ((uint32_t)__bfloat16_as_ushort(ly) << 16) | __bfloat16_as_ushort(lx);
}

// ---------------- prep: transposes + edge MLP hiddens + deg zero -----------
#define TR_BLOCKS 37
#define EH_BLOCKS ((EE + 255) / 256)

__global__ __launch_bounds__(256) void prep_kernel(
    const float* __restrict__ ea,
    const float* __restrict__ nn0_w1, const float* __restrict__ nn0_b1,
    const float* __restrict__ nn0_w2, const float* __restrict__ nn0_b2,
    const float* __restrict__ nn1_w1, const float* __restrict__ nn1_b1,
    const float* __restrict__ nn1_w2, const float* __restrict__ nn1_b2,
    const float* __restrict__ root0, const float* __restrict__ root1,
    const float* __restrict__ root2)
{
    int tid = threadIdx.x;
    int b = blockIdx.x;

    // zero degree histogram (consumed by csr_hist, next launch)
    {
        int gid = b * 256 + tid;
        if (gid < NN) g_deg[gid] = 0;
    }

    if (b < TR_BLOCKS) {
        __shared__ float ts[64 * 65];
        const float* src;
        float* dst;
        int D;
        if (b < 17)       { D = 32; src = (b < 16) ? nn0_w2 + b * 2048 : nn0_b2;
                            dst = g_WT0 + b * 64 * 32; }
        else if (b == 17) { D = 32; src = root0; dst = g_RT0; }
        else if (b < 35)  { int bb = b - 18; D = 64;
                            src = (bb < 16) ? nn1_w2 + bb * 4096 : nn1_b2;
                            dst = g_WT1 + bb * 64 * 64; }
        else if (b == 35) { D = 64; src = root1; dst = g_RT1; }
        else              { D = 64; src = root2; dst = g_RT2; }

        for (int idx = tid; idx < 64 * D; idx += 256) {
            int o = idx & 63, i = idx >> 6;
            ts[o * 65 + i] = src[i * 64 + o];
        }
        __syncthreads();
        for (int idx = tid; idx < 64 * D; idx += 256) {
            int i = idx & (D - 1), o = idx / D;
            dst[idx] = ts[o * 65 + i];
        }
        return;
    }

    __shared__ float sw0[FEDGE * HID], sw1[FEDGE * HID];
    __shared__ float sb0[HID], sb1[HID];
    if (tid < FEDGE * HID) { sw0[tid] = nn0_w1[tid]; sw1[tid] = nn1_w1[tid]; }
    if (tid < HID)         { sb0[tid] = nn0_b1[tid]; sb1[tid] = nn1_b1[tid]; }
    __syncthreads();

    int e = (b - TR_BLOCKS) * 256 + tid;
    if (e >= EE) return;
    const float4* p = reinterpret_cast<const float4*>(ea + (size_t)e * FEDGE);
    float4 v0 = p[0], v1 = p[1];
    float a[8] = {v0.x, v0.y, v0.z, v0.w, v1.x, v1.y, v1.z, v1.w};
#pragma unroll
    for (int h = 0; h < HID; h++) {
        float s0 = sb0[h], s1 = sb1[h];
#pragma unroll
        for (int j = 0; j < FEDGE; j++) {
            s0 += a[j] * sw0[j * HID + h];
            s1 += a[j] * sw1[j * HID + h];
        }
        g_h0[e * HID + h] = fmaxf(s0, 0.f);
        g_h1[e * HID + h] = fmaxf(s1, 0.f);
    }
}

// ---------------- CSR build -------------------------------------------------
__global__ __launch_bounds__(256) void csr_hist_kernel(const int* __restrict__ ei)
{
    int e = blockIdx.x * 256 + threadIdx.x;
    if (e < EE) atomicAdd(&g_deg[ei[e]], 1);
}

__global__ __launch_bounds__(1024) void csr_scan_kernel()
{
    __shared__ int ps[1024];
    int t = threadIdx.x;
    int base = t * 10;
    int dloc[10];
    int sum = 0;
#pragma unroll
    for (int j = 0; j < 10; j++) {
        int n = base + j;
        int d = (n < NN) ? g_deg[n] : 0;
        dloc[j] = d;
        sum += d;
    }
    ps[t] = sum;
    __syncthreads();
    for (int off = 1; off < 1024; off <<= 1) {
        int v = (t >= off) ? ps[t - off] : 0;
        __syncthreads();
        ps[t] += v;
        __syncthreads();
    }
    int run = ps[t] - sum;
#pragma unroll
    for (int j = 0; j < 10; j++) {
        int n = base + j;
        if (n < NN) { g_rowptr[n] = run; run += dloc[j]; }
    }
    if (t == 1023) g_rowptr[NN] = ps[1023];
    for (int i = t; i < NN; i += 1024) g_fill[i] = 0;
}

__global__ __launch_bounds__(256) void csr_scatter_kernel(const int* __restrict__ ei)
{
    int e = blockIdx.x * 256 + threadIdx.x;
    if (e >= EE) return;
    int src = ei[e];
    int dst = ei[EE + e];
    int pos = g_rowptr[src] + atomicAdd(&g_fill[src], 1);
    g_edst[pos] = dst;
    g_eid[pos]  = e;
}

// ---------------- fused HMMA GEMM (R5 structure, unchanged) ----------------
template <int D, int MODE>
__global__ __launch_bounds__(256, 2) void gemm_fused_kernel(
    const float* __restrict__ xin, const float* __restrict__ biasin)
{
    const int SD = D + 8;
    const int CPT = D / 8;
    extern __shared__ ushort smu[];
    ushort* Ah = smu;
    ushort* Al = Ah + 128 * SD;
    ushort* Bh = Al + 128 * SD;
    ushort* Bl = Bh + 64 * SD;
    __shared__ float sbias[64];

    const float* __restrict__ aggin = (MODE == 1) ? g_agg0 : g_agg1;
    const float* __restrict__ xrin  = (MODE == 1) ? g_xr0  : g_xr1;
    float* __restrict__ aggz  = (MODE == 0) ? g_agg0 : (MODE == 1 ? g_agg1 : g_agg2);
    float* __restrict__ xrout = (MODE == 0) ? g_xr0  : (MODE == 1 ? g_xr1  : g_xr2);
    const float* __restrict__ WT = (MODE == 0) ? g_WT0 : g_WT1;
    const float* __restrict__ RT = (MODE == 0) ? g_RT0 : (MODE == 1 ? g_RT1 : g_RT2);

    int tid = threadIdx.x, wid = tid >> 5, l = tid & 31;
    int wm = wid & 3, wn = wid >> 2;
    int m0 = blockIdx.y * 128;
    int t0 = blockIdx.x * 2;

    {
        int nthr = gridDim.x * gridDim.y * 256;
        for (int i = (blockIdx.y * gridDim.x + blockIdx.x) * 256 + tid;
             i < NN * EMB; i += nthr)
            aggz[i] = 0.f;
    }
    if (MODE && tid < 64) sbias[tid] = biasin[tid];
    if (MODE) __syncthreads();

    // ---- stage A once (full D), fp32 -> bf16 hi/lo ----
    for (int idx = tid; idx < 128 * CPT; idx += 256) {
        int r = idx / CPT, cb = (idx % CPT) * 8;
        int n = m0 + r;
        bool v = (n < NN);
        float vals[8];
        if (MODE == 0) {
            float4 a0 = make_float4(0.f, 0.f, 0.f, 0.f), a1 = a0;
            if (v) {
                a0 = *reinterpret_cast<const float4*>(xin + (size_t)n * D + cb);
                a1 = *reinterpret_cast<const float4*>(xin + (size_t)n * D + cb + 4);
            }
            vals[0]=a0.x; vals[1]=a0.y; vals[2]=a0.z; vals[3]=a0.w;
            vals[4]=a1.x; vals[5]=a1.y; vals[6]=a1.z; vals[7]=a1.w;
        } else {
            float4 g0 = make_float4(0.f,0.f,0.f,0.f), g1 = g0, r0 = g0, r1 = g0;
            if (v) {
                g0 = *reinterpret_cast<const float4*>(aggin + (size_t)n * EMB + cb);
                g1 = *reinterpret_cast<const float4*>(aggin + (size_t)n * EMB + cb + 4);
                r0 = *reinterpret_cast<const float4*>(xrin + (size_t)n * EMB + cb);
                r1 = *reinterpret_cast<const float4*>(xrin + (size_t)n * EMB + cb + 4);
            }
            vals[0] = fmaxf(g0.x + r0.x + sbias[cb+0], 0.f);
            vals[1] = fmaxf(g0.y + r0.y + sbias[cb+1], 0.f);
            vals[2] = fmaxf(g0.z + r0.z + sbias[cb+2], 0.f);
            vals[3] = fmaxf(g0.w + r0.w + sbias[cb+3], 0.f);
            vals[4] = fmaxf(g1.x + r1.x + sbias[cb+4], 0.f);
            vals[5] = fmaxf(g1.y + r1.y + sbias[cb+5], 0.f);
            vals[6] = fmaxf(g1.z + r1.z + sbias[cb+6], 0.f);
            vals[7] = fmaxf(g1.w + r1.w + sbias[cb+7], 0.f);
        }
        uint32_t* ah32 = reinterpret_cast<uint32_t*>(Ah);
        uint32_t* al32 = reinterpret_cast<uint32_t*>(Al);
        int base = (r * SD + cb) >> 1;
#pragma unroll
        for (int j = 0; j < 4; j++) {
            uint32_t hi, lo;
            split_pack(vals[2*j], vals[2*j+1], hi, lo);
            ah32[base + j] = hi;
            al32[base + j] = lo;
        }
    }

    uint32_t aAh = smem_u32(Ah), aAl = smem_u32(Al);
    uint32_t aBh = smem_u32(Bh), aBl = smem_u32(Bl);

#pragma unroll
    for (int ti = 0; ti < 2; ti++) {
        int ct = t0 + ti;
        const float* __restrict__ bsrc = (ct == 17) ? RT : WT + (size_t)ct * 64 * D;

        for (int idx = tid; idx < 64 * CPT; idx += 256) {
            int r = idx / CPT, cb = (idx % CPT) * 8;
            float4 b0 = *reinterpret_cast<const float4*>(bsrc + r * D + cb);
            float4 b1 = *reinterpret_cast<const float4*>(bsrc + r * D + cb + 4);
            float bv[8] = {b0.x,b0.y,b0.z,b0.w,b1.x,b1.y,b1.z,b1.w};
            uint32_t* bh32 = reinterpret_cast<uint32_t*>(Bh);
            uint32_t* bl32 = reinterpret_cast<uint32_t*>(Bl);
            int base = (r * SD + cb) >> 1;
#pragma unroll
            for (int j = 0; j < 4; j++) {
                uint32_t hi, lo;
                split_pack(bv[2*j], bv[2*j+1], hi, lo);
                bh32[base + j] = hi;
                bl32[base + j] = lo;
            }
        }
        __syncthreads();

        float acc[2][4][4];
#pragma unroll
        for (int mi = 0; mi < 2; mi++)
#pragma unroll
            for (int nf = 0; nf < 4; nf++)
#pragma unroll
                for (int q = 0; q < 4; q++) acc[mi][nf][q] = 0.f;

#pragma unroll
        for (int ks = 0; ks < D; ks += 16) {
            uint32_t ahf[2][4], alf[2][4];
#pragma unroll
            for (int mi = 0; mi < 2; mi++) {
                uint32_t off = ((uint32_t)(wm * 32 + mi * 16 + (l & 15)) * SD
                                + ks + (l >> 4) * 8) * 2;
                ldmx4(ahf[mi], aAh + off);
                ldmx4(alf[mi], aAl + off);
            }
            uint32_t bhf[8], blf[8];
#pragma unroll
            for (int g = 0; g < 2; g++) {
                uint32_t off = ((uint32_t)(wn * 32 + g * 16 + (l & 7) + ((l >> 4) & 1) * 8) * SD
                                + ks + ((l >> 3) & 1) * 8) * 2;
                ldmx4(bhf + g * 4, aBh + off);
                ldmx4(blf + g * 4, aBl + off);
            }
#pragma unroll
            for (int mi = 0; mi < 2; mi++)
#pragma unroll
                for (int nf = 0; nf < 4; nf++) {
                    mma_bf16(acc[mi][nf], ahf[mi], bhf[nf*2], bhf[nf*2+1]);
                    mma_bf16(acc[mi][nf], alf[mi], bhf[nf*2], bhf[nf*2+1]);
                    mma_bf16(acc[mi][nf], ahf[mi], blf[nf*2], blf[nf*2+1]);
                }
        }

#pragma unroll
        for (int mi = 0; mi < 2; mi++)
#pragma unroll
            for (int nf = 0; nf < 4; nf++) {
                int gr = m0 + wm * 32 + mi * 16 + (l >> 2);
                int co = ct * 64 + wn * 32 + nf * 8 + 2 * (l & 3);
                float2 v0 = make_float2(acc[mi][nf][0], acc[mi][nf][1]);
                float2 v1 = make_float2(acc[mi][nf][2], acc[mi][nf][3]);
                if (ct < 17) {
                    if (gr < NN)
                        *reinterpret_cast<float2*>(g_PQ + (size_t)gr * NCOL + co) = v0;
                    if (gr + 8 < NN)
                        *reinterpret_cast<float2*>(g_PQ + (size_t)(gr + 8) * NCOL + co) = v1;
                } else {
                    int cr = co - NCOL;
                    if (gr < NN)
                        *reinterpret_cast<float2*>(xrout + (size_t)gr * EMB + cr) = v0;
                    if (gr + 8 < NN)
                        *reinterpret_cast<float2*>(xrout + (size_t)(gr + 8) * EMB + cr) = v1;
                }
            }
        __syncthreads();
    }
}

// ---------------- CSR edge message: one warp per SOURCE node ---------------
// P[src] row loaded once into registers (17 float2 per lane), reused for
// every outgoing edge. Per edge: gather h, shfl-broadcast, red.v2 scatter.
__global__ __launch_bounds__(256) void edge_csr_kernel(int conv)
{
    int warp = blockIdx.x * 8 + (threadIdx.x >> 5);
    int lane = threadIdx.x & 31;
    if (warp >= NN) return;

    int beg = g_rowptr[warp];
    int end = g_rowptr[warp + 1];
    if (beg == end) return;

    const float* __restrict__ hsrc = conv ? g_h1 : g_h0;
    float* __restrict__ agg = (conv == 0) ? g_agg0 : (conv == 1 ? g_agg1 : g_agg2);

    const float* __restrict__ P = g_PQ + (size_t)warp * NCOL;
    float2 q = *reinterpret_cast<const float2*>(P + QOFF + lane * 2);
    float2 p[HID];
#pragma unroll
    for (int h = 0; h < HID; h++)
        p[h] = *reinterpret_cast<const float2*>(P + h * EMB + lane * 2);

    for (int i = beg; i < end; i++) {
        int dst = g_edst[i];
        int e   = g_eid[i];
        float hv = (lane < HID) ? hsrc[(size_t)e * HID + lane] : 0.f;
        float2 acc = q;
#pragma unroll
        for (int h = 0; h < HID; h++) {
            float w = __shfl_sync(0xffffffffu, hv, h);
            acc.x += w * p[h].x;
            acc.y += w * p[h].y;
        }
        float* a = agg + (size_t)dst * EMB + lane * 2;
        asm volatile("red.global.add.v2.f32 [%0], {%1,%2};"
                     :: "l"(a), "f"(acc.x), "f"(acc.y) : "memory");
    }
}

// ---------------- pool (fused final combine; batch sorted, x >= 0) --------
__global__ __launch_bounds__(256) void pool_kernel(const int* __restrict__ batch,
                                                   const float* __restrict__ bias2)
{
    int tid = threadIdx.x;
    int o = tid & 63, seg = tid >> 6;
    int n0 = blockIdx.x * 32 + seg * 8;
    float bz = __ldg(bias2 + o);
    int curb = -1;
    float m = 0.f;
    for (int k = 0; k < 8; k++) {
        int n = n0 + k;
        if (n >= NN) break;
        int b = batch[n];
        if (b != curb) {
            if (curb >= 0)
                atomicMax(reinterpret_cast<unsigned*>(g_pool + (size_t)curb * EMB + o),
                          __float_as_uint(m));
            curb = b;
            m = 0.f;
        }
        float x = fmaxf(g_agg2[(size_t)n * EMB + o] + g_xr2[(size_t)n * EMB + o] + bz, 0.f);
        m = fmaxf(m, x);
    }
    if (curb >= 0)
        atomicMax(reinterpret_cast<unsigned*>(g_pool + (size_t)curb * EMB + o),
                  __float_as_uint(m));
}

// ---------------- head -----------------------------------------------------
__global__ __launch_bounds__(64) void head_kernel(
    const float* __restrict__ lin0w, const float* __restrict__ lin0b,
    const float* __restrict__ lin1w, const float* __restrict__ lin1b,
    float* __restrict__ out)
{
    __shared__ float pg[EMB];
    __shared__ float red[EMB];
    int g = blockIdx.x, o = threadIdx.x;
    pg[o] = g_pool[(size_t)g * EMB + o];
    __syncthreads();

    float h = lin0b[o];
#pragma unroll
    for (int i = 0; i < EMB; i++) h += pg[i] * lin0w[i * EMB + o];
    red[o] = h * lin1w[o];
    __syncthreads();
#pragma unroll
    for (int s = 32; s > 0; s >>= 1) {
        if (o < s) red[o] += red[o + s];
        __syncthreads();
    }
    if (o == 0) out[g] = red[0] + lin1b[0];
}

// ---------------- launch ----------------------------------------------------
extern "C" void kernel_launch(void* const* d_in, const int* in_sizes, int n_in,
                              void* d_out, int out_size)
{
    const float* x_p    = (const float*)d_in[0];
    const float* ea     = (const float*)d_in[2];
    const int*   ei     = (const int*)  d_in[4];
    const int*   batch  = (const int*)  d_in[5];
    const float* nn0_w1 = (const float*)d_in[6];
    const float* nn0_b1 = (const float*)d_in[7];
    const float* nn0_w2 = (const float*)d_in[8];
    const float* nn0_b2 = (const float*)d_in[9];
    const float* nn1_w1 = (const float*)d_in[10];
    const float* nn1_b1 = (const float*)d_in[11];
    const float* nn1_w2 = (const float*)d_in[12];
    const float* nn1_b2 = (const float*)d_in[13];
    const float* root0  = (const float*)d_in[14];
    const float* bias0  = (const float*)d_in[15];
    const float* root1  = (const float*)d_in[16];
    const float* bias1  = (const float*)d_in[17];
    const float* root2  = (const float*)d_in[18];
    const float* bias2  = (const float*)d_in[19];
    const float* lin0_w = (const float*)d_in[20];
    const float* lin0_b = (const float*)d_in[21];
    const float* lin1_w = (const float*)d_in[22];
    const float* lin1_b = (const float*)d_in[23];
    float* out = (float*)d_out;

    int smem32 = 128 * 40 * 4 + 64 * 40 * 4;   // 30720
    int smem64 = 128 * 72 * 4 + 64 * 72 * 4;   // 55296

    static bool attr_done = false;
    if (!attr_done) {
        cudaFuncSetAttribute(gemm_fused_kernel<64, 1>,
                             cudaFuncAttributeMaxDynamicSharedMemorySize, smem64);
        cudaFuncSetAttribute(gemm_fused_kernel<64, 2>,
                             cudaFuncAttributeMaxDynamicSharedMemorySize, smem64);
        attr_done = true;
    }

    dim3 gemm_grid(9, (NN + 127) / 128);
    int eblocks = (EE + 255) / 256;
    int nwarp_blocks = (NN + 7) / 8;

    // prep (also zeroes g_deg) + CSR build (replay-invariant, rebuilt per call)
    prep_kernel<<<TR_BLOCKS + EH_BLOCKS, 256>>>(
        ea, nn0_w1, nn0_b1, nn0_w2, nn0_b2, nn1_w1, nn1_b1, nn1_w2, nn1_b2,
        root0, root1, root2);
    csr_hist_kernel<<<eblocks, 256>>>(ei);
    csr_scan_kernel<<<1, 1024>>>();
    csr_scatter_kernel<<<eblocks, 256>>>(ei);

    // ---- conv0 ----
    gemm_fused_kernel<32, 0><<<gemm_grid, 256, smem32>>>(x_p, bias0);
    edge_csr_kernel<<<nwarp_blocks, 256>>>(0);

    // ---- conv1 ----
    gemm_fused_kernel<64, 1><<<gemm_grid, 256, smem64>>>(nullptr, bias0);
    edge_csr_kernel<<<nwarp_blocks, 256>>>(1);

    // ---- conv2 ----
    gemm_fused_kernel<64, 2><<<gemm_grid, 256, smem64>>>(nullptr, bias1);
    edge_csr_kernel<<<nwarp_blocks, 256>>>(2);

    // ---- pool (fused final combine) + head ----
    pool_kernel<<<(NN + 31) / 32, 256>>>(batch, bias2);
    head_kernel<<<NG, 64>>>(lin0_w, lin0_b, lin1_w, lin1_b, out);
}

// round 9
// speedup vs baseline: 1.0936x; 1.0936x over previous
#include <cuda_runtime.h>
#include <cuda_bf16.h>
#include <cstdint>

#define NN      10000
#define EE      30000
#define FEDGE   8
#define EMB     64
#define HID     16
#define NG      64
#define NCOL    1088   // 1024 P | 64 Q
#define QOFF    1024

// ---------------- scratch (device globals) --------------------------------
__device__ __align__(128) float g_h0[EE * HID];
__device__ __align__(128) float g_h1[EE * HID];
__device__ __align__(128) float g_PQ[(size_t)NN * NCOL];
__device__ __align__(128) float g_agg0[NN * EMB];
__device__ __align__(128) float g_agg1[NN * EMB];
__device__ __align__(128) float g_agg2[NN * EMB];
__device__ __align__(128) float g_xr0[NN * EMB];
__device__ __align__(128) float g_xr1[NN * EMB];
__device__ __align__(128) float g_xr2[NN * EMB];
__device__ __align__(128) float g_WT0[NCOL * 32];  // [c][i] P+Q, conv0
__device__ __align__(128) float g_WT1[NCOL * 64];  // [c][i] P+Q, convs 1&2
__device__ __align__(128) float g_RT0[64 * 32];    // [o][i] rootT
__device__ __align__(128) float g_RT1[64 * 64];
__device__ __align__(128) float g_RT2[64 * 64];
__device__ __align__(128) float g_pool[NG * EMB];
// src-sorted edge order (rebuilt every replay from constant inputs)
__device__ __align__(128) int g_deg[NN];
__device__ __align__(128) int g_fill[NN];
__device__ __align__(128) int g_rowptr[NN];
__device__ __align__(128) int g_esrc[EE];
__device__ __align__(128) int g_edst[EE];
__device__ __align__(128) int g_eid[EE];

// ---------------- helpers --------------------------------------------------
__device__ __forceinline__ uint32_t smem_u32(const void* p) {
    uint32_t a;
    asm("{ .reg .u64 t; cvta.to.shared.u64 t, %1; cvt.u32.u64 %0, t; }" : "=r"(a) : "l"(p));
    return a;
}
__device__ __forceinline__ void ldmx4(uint32_t* r, uint32_t addr) {
    asm volatile("ldmatrix.sync.aligned.m8n8.x4.shared.b16 {%0,%1,%2,%3}, [%4];"
        : "=r"(r[0]), "=r"(r[1]), "=r"(r[2]), "=r"(r[3]) : "r"(addr));
}
__device__ __forceinline__ void mma_bf16(float* d, const uint32_t* a,
                                         uint32_t b0, uint32_t b1) {
    asm volatile("mma.sync.aligned.m16n8k16.row.col.f32.bf16.bf16.f32 "
        "{%0,%1,%2,%3}, {%4,%5,%6,%7}, {%8,%9}, {%0,%1,%2,%3};"
        : "+f"(d[0]), "+f"(d[1]), "+f"(d[2]), "+f"(d[3])
        : "r"(a[0]), "r"(a[1]), "r"(a[2]), "r"(a[3]), "r"(b0), "r"(b1));
}
__device__ __forceinline__ void split_pack(float fx, float fy,
                                           uint32_t& hi, uint32_t& lo) {
    __nv_bfloat16 hx = __float2bfloat16(fx), hy = __float2bfloat16(fy);
    hi = ((uint32_t)__bfloat16_as_ushort(hy) << 16) | __bfloat16_as_ushort(hx);
    __nv_bfloat16 lx = __float2bfloat16(fx - __bfloat162float(hx));
    __nv_bfloat16 ly = __float2bfloat16(fy - __bfloat162float(hy));
    lo = ((uint32_t)__bfloat16_as_ushort(ly) << 16) | __bfloat16_as_ushort(lx);
}

// ---------------- prep: transposes + edge MLP hiddens + deg zero -----------
#define TR_BLOCKS 37
#define EH_BLOCKS ((EE + 255) / 256)

__global__ __launch_bounds__(256) void prep_kernel(
    const float* __restrict__ ea,
    const float* __restrict__ nn0_w1, const float* __restrict__ nn0_b1,
    const float* __restrict__ nn0_w2, const float* __restrict__ nn0_b2,
    const float* __restrict__ nn1_w1, const float* __restrict__ nn1_b1,
    const float* __restrict__ nn1_w2, const float* __restrict__ nn1_b2,
    const float* __restrict__ root0, const float* __restrict__ root1,
    const float* __restrict__ root2)
{
    int tid = threadIdx.x;
    int b = blockIdx.x;

    // zero degree histogram (consumed by csr_hist, next launch)
    {
        int gid = b * 256 + tid;
        if (gid < NN) g_deg[gid] = 0;
    }

    if (b < TR_BLOCKS) {
        __shared__ float ts[64 * 65];
        const float* src;
        float* dst;
        int D;
        if (b < 17)       { D = 32; src = (b < 16) ? nn0_w2 + b * 2048 : nn0_b2;
                            dst = g_WT0 + b * 64 * 32; }
        else if (b == 17) { D = 32; src = root0; dst = g_RT0; }
        else if (b < 35)  { int bb = b - 18; D = 64;
                            src = (bb < 16) ? nn1_w2 + bb * 4096 : nn1_b2;
                            dst = g_WT1 + bb * 64 * 64; }
        else if (b == 35) { D = 64; src = root1; dst = g_RT1; }
        else              { D = 64; src = root2; dst = g_RT2; }

        for (int idx = tid; idx < 64 * D; idx += 256) {
            int o = idx & 63, i = idx >> 6;
            ts[o * 65 + i] = src[i * 64 + o];
        }
        __syncthreads();
        for (int idx = tid; idx < 64 * D; idx += 256) {
            int i = idx & (D - 1), o = idx / D;
            dst[idx] = ts[o * 65 + i];
        }
        return;
    }

    __shared__ float sw0[FEDGE * HID], sw1[FEDGE * HID];
    __shared__ float sb0[HID], sb1[HID];
    if (tid < FEDGE * HID) { sw0[tid] = nn0_w1[tid]; sw1[tid] = nn1_w1[tid]; }
    if (tid < HID)         { sb0[tid] = nn0_b1[tid]; sb1[tid] = nn1_b1[tid]; }
    __syncthreads();

    int e = (b - TR_BLOCKS) * 256 + tid;
    if (e >= EE) return;
    const float4* p = reinterpret_cast<const float4*>(ea + (size_t)e * FEDGE);
    float4 v0 = p[0], v1 = p[1];
    float a[8] = {v0.x, v0.y, v0.z, v0.w, v1.x, v1.y, v1.z, v1.w};
#pragma unroll
    for (int h = 0; h < HID; h++) {
        float s0 = sb0[h], s1 = sb1[h];
#pragma unroll
        for (int j = 0; j < FEDGE; j++) {
            s0 += a[j] * sw0[j * HID + h];
            s1 += a[j] * sw1[j * HID + h];
        }
        g_h0[e * HID + h] = fmaxf(s0, 0.f);
        g_h1[e * HID + h] = fmaxf(s1, 0.f);
    }
}

// ---------------- edge sort by src (hist -> scan -> scatter) ---------------
__global__ __launch_bounds__(256) void csr_hist_kernel(const int* __restrict__ ei)
{
    int e = blockIdx.x * 256 + threadIdx.x;
    if (e < EE) atomicAdd(&g_deg[ei[e]], 1);
}

__global__ __launch_bounds__(1024) void csr_scan_kernel()
{
    __shared__ int ps[1024];
    int t = threadIdx.x;
    int base = t * 10;
    int dloc[10];
    int sum = 0;
#pragma unroll
    for (int j = 0; j < 10; j++) {
        int n = base + j;
        int d = (n < NN) ? g_deg[n] : 0;
        dloc[j] = d;
        sum += d;
    }
    ps[t] = sum;
    __syncthreads();
    for (int off = 1; off < 1024; off <<= 1) {
        int v = (t >= off) ? ps[t - off] : 0;
        __syncthreads();
        ps[t] += v;
        __syncthreads();
    }
    int run = ps[t] - sum;
#pragma unroll
    for (int j = 0; j < 10; j++) {
        int n = base + j;
        if (n < NN) { g_rowptr[n] = run; run += dloc[j]; }
    }
    for (int i = t; i < NN; i += 1024) g_fill[i] = 0;
}

__global__ __launch_bounds__(256) void csr_scatter_kernel(const int* __restrict__ ei)
{
    int e = blockIdx.x * 256 + threadIdx.x;
    if (e >= EE) return;
    int src = ei[e];
    int dst = ei[EE + e];
    int pos = g_rowptr[src] + atomicAdd(&g_fill[src], 1);
    g_esrc[pos] = src;
    g_edst[pos] = dst;
    g_eid[pos]  = e;
}

// ---------------- fused HMMA GEMM (R5 structure, unchanged) ----------------
template <int D, int MODE>
__global__ __launch_bounds__(256, 2) void gemm_fused_kernel(
    const float* __restrict__ xin, const float* __restrict__ biasin)
{
    const int SD = D + 8;
    const int CPT = D / 8;
    extern __shared__ ushort smu[];
    ushort* Ah = smu;
    ushort* Al = Ah + 128 * SD;
    ushort* Bh = Al + 128 * SD;
    ushort* Bl = Bh + 64 * SD;
    __shared__ float sbias[64];

    const float* __restrict__ aggin = (MODE == 1) ? g_agg0 : g_agg1;
    const float* __restrict__ xrin  = (MODE == 1) ? g_xr0  : g_xr1;
    float* __restrict__ aggz  = (MODE == 0) ? g_agg0 : (MODE == 1 ? g_agg1 : g_agg2);
    float* __restrict__ xrout = (MODE == 0) ? g_xr0  : (MODE == 1 ? g_xr1  : g_xr2);
    const float* __restrict__ WT = (MODE == 0) ? g_WT0 : g_WT1;
    const float* __restrict__ RT = (MODE == 0) ? g_RT0 : (MODE == 1 ? g_RT1 : g_RT2);

    int tid = threadIdx.x, wid = tid >> 5, l = tid & 31;
    int wm = wid & 3, wn = wid >> 2;
    int m0 = blockIdx.y * 128;
    int t0 = blockIdx.x * 2;

    {
        int nthr = gridDim.x * gridDim.y * 256;
        for (int i = (blockIdx.y * gridDim.x + blockIdx.x) * 256 + tid;
             i < NN * EMB; i += nthr)
            aggz[i] = 0.f;
    }
    if (MODE && tid < 64) sbias[tid] = biasin[tid];
    if (MODE) __syncthreads();

    // ---- stage A once (full D), fp32 -> bf16 hi/lo ----
    for (int idx = tid; idx < 128 * CPT; idx += 256) {
        int r = idx / CPT, cb = (idx % CPT) * 8;
        int n = m0 + r;
        bool v = (n < NN);
        float vals[8];
        if (MODE == 0) {
            float4 a0 = make_float4(0.f, 0.f, 0.f, 0.f), a1 = a0;
            if (v) {
                a0 = *reinterpret_cast<const float4*>(xin + (size_t)n * D + cb);
                a1 = *reinterpret_cast<const float4*>(xin + (size_t)n * D + cb + 4);
            }
            vals[0]=a0.x; vals[1]=a0.y; vals[2]=a0.z; vals[3]=a0.w;
            vals[4]=a1.x; vals[5]=a1.y; vals[6]=a1.z; vals[7]=a1.w;
        } else {
            float4 g0 = make_float4(0.f,0.f,0.f,0.f), g1 = g0, r0 = g0, r1 = g0;
            if (v) {
                g0 = *reinterpret_cast<const float4*>(aggin + (size_t)n * EMB + cb);
                g1 = *reinterpret_cast<const float4*>(aggin + (size_t)n * EMB + cb + 4);
                r0 = *reinterpret_cast<const float4*>(xrin + (size_t)n * EMB + cb);
                r1 = *reinterpret_cast<const float4*>(xrin + (size_t)n * EMB + cb + 4);
            }
            vals[0] = fmaxf(g0.x + r0.x + sbias[cb+0], 0.f);
            vals[1] = fmaxf(g0.y + r0.y + sbias[cb+1], 0.f);
            vals[2] = fmaxf(g0.z + r0.z + sbias[cb+2], 0.f);
            vals[3] = fmaxf(g0.w + r0.w + sbias[cb+3], 0.f);
            vals[4] = fmaxf(g1.x + r1.x + sbias[cb+4], 0.f);
            vals[5] = fmaxf(g1.y + r1.y + sbias[cb+5], 0.f);
            vals[6] = fmaxf(g1.z + r1.z + sbias[cb+6], 0.f);
            vals[7] = fmaxf(g1.w + r1.w + sbias[cb+7], 0.f);
        }
        uint32_t* ah32 = reinterpret_cast<uint32_t*>(Ah);
        uint32_t* al32 = reinterpret_cast<uint32_t*>(Al);
        int base = (r * SD + cb) >> 1;
#pragma unroll
        for (int j = 0; j < 4; j++) {
            uint32_t hi, lo;
            split_pack(vals[2*j], vals[2*j+1], hi, lo);
            ah32[base + j] = hi;
            al32[base + j] = lo;
        }
    }

    uint32_t aAh = smem_u32(Ah), aAl = smem_u32(Al);
    uint32_t aBh = smem_u32(Bh), aBl = smem_u32(Bl);

#pragma unroll
    for (int ti = 0; ti < 2; ti++) {
        int ct = t0 + ti;
        const float* __restrict__ bsrc = (ct == 17) ? RT : WT + (size_t)ct * 64 * D;

        for (int idx = tid; idx < 64 * CPT; idx += 256) {
            int r = idx / CPT, cb = (idx % CPT) * 8;
            float4 b0 = *reinterpret_cast<const float4*>(bsrc + r * D + cb);
            float4 b1 = *reinterpret_cast<const float4*>(bsrc + r * D + cb + 4);
            float bv[8] = {b0.x,b0.y,b0.z,b0.w,b1.x,b1.y,b1.z,b1.w};
            uint32_t* bh32 = reinterpret_cast<uint32_t*>(Bh);
            uint32_t* bl32 = reinterpret_cast<uint32_t*>(Bl);
            int base = (r * SD + cb) >> 1;
#pragma unroll
            for (int j = 0; j < 4; j++) {
                uint32_t hi, lo;
                split_pack(bv[2*j], bv[2*j+1], hi, lo);
                bh32[base + j] = hi;
                bl32[base + j] = lo;
            }
        }
        __syncthreads();

        float acc[2][4][4];
#pragma unroll
        for (int mi = 0; mi < 2; mi++)
#pragma unroll
            for (int nf = 0; nf < 4; nf++)
#pragma unroll
                for (int q = 0; q < 4; q++) acc[mi][nf][q] = 0.f;

#pragma unroll
        for (int ks = 0; ks < D; ks += 16) {
            uint32_t ahf[2][4], alf[2][4];
#pragma unroll
            for (int mi = 0; mi < 2; mi++) {
                uint32_t off = ((uint32_t)(wm * 32 + mi * 16 + (l & 15)) * SD
                                + ks + (l >> 4) * 8) * 2;
                ldmx4(ahf[mi], aAh + off);
                ldmx4(alf[mi], aAl + off);
            }
            uint32_t bhf[8], blf[8];
#pragma unroll
            for (int g = 0; g < 2; g++) {
                uint32_t off = ((uint32_t)(wn * 32 + g * 16 + (l & 7) + ((l >> 4) & 1) * 8) * SD
                                + ks + ((l >> 3) & 1) * 8) * 2;
                ldmx4(bhf + g * 4, aBh + off);
                ldmx4(blf + g * 4, aBl + off);
            }
#pragma unroll
            for (int mi = 0; mi < 2; mi++)
#pragma unroll
                for (int nf = 0; nf < 4; nf++) {
                    mma_bf16(acc[mi][nf], ahf[mi], bhf[nf*2], bhf[nf*2+1]);
                    mma_bf16(acc[mi][nf], alf[mi], bhf[nf*2], bhf[nf*2+1]);
                    mma_bf16(acc[mi][nf], ahf[mi], blf[nf*2], blf[nf*2+1]);
                }
        }

#pragma unroll
        for (int mi = 0; mi < 2; mi++)
#pragma unroll
            for (int nf = 0; nf < 4; nf++) {
                int gr = m0 + wm * 32 + mi * 16 + (l >> 2);
                int co = ct * 64 + wn * 32 + nf * 8 + 2 * (l & 3);
                float2 v0 = make_float2(acc[mi][nf][0], acc[mi][nf][1]);
                float2 v1 = make_float2(acc[mi][nf][2], acc[mi][nf][3]);
                if (ct < 17) {
                    if (gr < NN)
                        *reinterpret_cast<float2*>(g_PQ + (size_t)gr * NCOL + co) = v0;
                    if (gr + 8 < NN)
                        *reinterpret_cast<float2*>(g_PQ + (size_t)(gr + 8) * NCOL + co) = v1;
                } else {
                    int cr = co - NCOL;
                    if (gr < NN)
                        *reinterpret_cast<float2*>(xrout + (size_t)gr * EMB + cr) = v0;
                    if (gr + 8 < NN)
                        *reinterpret_cast<float2*>(xrout + (size_t)(gr + 8) * EMB + cr) = v1;
                }
            }
        __syncthreads();
    }
}

// ---------------- edge message (R5 body, src-sorted order) -----------------
// 2 edges per warp via half-warps; consecutive slots share src rows -> L1 hits.
__global__ __launch_bounds__(256) void edge_msg_kernel(int conv)
{
    int gw   = (blockIdx.x * 256 + threadIdx.x) >> 5;
    int lane = threadIdx.x & 31;
    int slot = gw * 2 + (lane >> 4);
    int sub  = lane & 15;
    if (slot >= EE) return;

    const float* __restrict__ hsrc = conv ? g_h1 : g_h0;
    float* __restrict__ agg = (conv == 0) ? g_agg0 : (conv == 1 ? g_agg1 : g_agg2);

    int src = g_esrc[slot];
    int dst = g_edst[slot];
    int e   = g_eid[slot];
    float hv = hsrc[(size_t)e * HID + sub];

    const float* __restrict__ P = g_PQ + (size_t)src * NCOL;
    float4 acc = *reinterpret_cast<const float4*>(P + QOFF + sub * 4);
#pragma unroll
    for (int h = 0; h < HID; h++) {
        float w = __shfl_sync(0xffffffffu, hv, (lane & 16) | h);
        float4 f = *reinterpret_cast<const float4*>(P + h * EMB + sub * 4);
        acc.x += w * f.x; acc.y += w * f.y; acc.z += w * f.z; acc.w += w * f.w;
    }
    float* a = agg + (size_t)dst * EMB + sub * 4;
    asm volatile("red.global.add.v4.f32 [%0], {%1,%2,%3,%4};"
                 :: "l"(a), "f"(acc.x), "f"(acc.y), "f"(acc.z), "f"(acc.w)
                 : "memory");
}

// ---------------- pool (fused final combine; batch sorted, x >= 0) --------
__global__ __launch_bounds__(256) void pool_kernel(const int* __restrict__ batch,
                                                   const float* __restrict__ bias2)
{
    int tid = threadIdx.x;
    int o = tid & 63, seg = tid >> 6;
    int n0 = blockIdx.x * 32 + seg * 8;
    float bz = __ldg(bias2 + o);
    int curb = -1;
    float m = 0.f;
    for (int k = 0; k < 8; k++) {
        int n = n0 + k;
        if (n >= NN) break;
        int b = batch[n];
        if (b != curb) {
            if (curb >= 0)
                atomicMax(reinterpret_cast<unsigned*>(g_pool + (size_t)curb * EMB + o),
                          __float_as_uint(m));
            curb = b;
            m = 0.f;
        }
        float x = fmaxf(g_agg2[(size_t)n * EMB + o] + g_xr2[(size_t)n * EMB + o] + bz, 0.f);
        m = fmaxf(m, x);
    }
    if (curb >= 0)
        atomicMax(reinterpret_cast<unsigned*>(g_pool + (size_t)curb * EMB + o),
                  __float_as_uint(m));
}

// ---------------- head -----------------------------------------------------
__global__ __launch_bounds__(64) void head_kernel(
    const float* __restrict__ lin0w, const float* __restrict__ lin0b,
    const float* __restrict__ lin1w, const float* __restrict__ lin1b,
    float* __restrict__ out)
{
    __shared__ float pg[EMB];
    __shared__ float red[EMB];
    int g = blockIdx.x, o = threadIdx.x;
    pg[o] = g_pool[(size_t)g * EMB + o];
    __syncthreads();

    float h = lin0b[o];
#pragma unroll
    for (int i = 0; i < EMB; i++) h += pg[i] * lin0w[i * EMB + o];
    red[o] = h * lin1w[o];
    __syncthreads();
#pragma unroll
    for (int s = 32; s > 0; s >>= 1) {
        if (o < s) red[o] += red[o + s];
        __syncthreads();
    }
    if (o == 0) out[g] = red[0] + lin1b[0];
}

// ---------------- launch ----------------------------------------------------
extern "C" void kernel_launch(void* const* d_in, const int* in_sizes, int n_in,
                              void* d_out, int out_size)
{
    const float* x_p    = (const float*)d_in[0];
    const float* ea     = (const float*)d_in[2];
    const int*   ei     = (const int*)  d_in[4];
    const int*   batch  = (const int*)  d_in[5];
    const float* nn0_w1 = (const float*)d_in[6];
    const float* nn0_b1 = (const float*)d_in[7];
    const float* nn0_w2 = (const float*)d_in[8];
    const float* nn0_b2 = (const float*)d_in[9];
    const float* nn1_w1 = (const float*)d_in[10];
    const float* nn1_b1 = (const float*)d_in[11];
    const float* nn1_w2 = (const float*)d_in[12];
    const float* nn1_b2 = (const float*)d_in[13];
    const float* root0  = (const float*)d_in[14];
    const float* bias0  = (const float*)d_in[15];
    const float* root1  = (const float*)d_in[16];
    const float* bias1  = (const float*)d_in[17];
    const float* root2  = (const float*)d_in[18];
    const float* bias2  = (const float*)d_in[19];
    const float* lin0_w = (const float*)d_in[20];
    const float* lin0_b = (const float*)d_in[21];
    const float* lin1_w = (const float*)d_in[22];
    const float* lin1_b = (const float*)d_in[23];
    float* out = (float*)d_out;

    int smem32 = 128 * 40 * 4 + 64 * 40 * 4;   // 30720
    int smem64 = 128 * 72 * 4 + 64 * 72 * 4;   // 55296

    static bool attr_done = false;
    if (!attr_done) {
        cudaFuncSetAttribute(gemm_fused_kernel<64, 1>,
                             cudaFuncAttributeMaxDynamicSharedMemorySize, smem64);
        cudaFuncSetAttribute(gemm_fused_kernel<64, 2>,
                             cudaFuncAttributeMaxDynamicSharedMemorySize, smem64);
        attr_done = true;
    }

    dim3 gemm_grid(9, (NN + 127) / 128);
    int eblocks = (EE + 255) / 256;
    int msg_blocks = EE / 16;

    // prep (zeroes g_deg) + src-sort build (replay-invariant, rebuilt per call)
    prep_kernel<<<TR_BLOCKS + EH_BLOCKS, 256>>>(
        ea, nn0_w1, nn0_b1, nn0_w2, nn0_b2, nn1_w1, nn1_b1, nn1_w2, nn1_b2,
        root0, root1, root2);
    csr_hist_kernel<<<eblocks, 256>>>(ei);
    csr_scan_kernel<<<1, 1024>>>();
    csr_scatter_kernel<<<eblocks, 256>>>(ei);

    // ---- conv0 ----
    gemm_fused_kernel<32, 0><<<gemm_grid, 256, smem32>>>(x_p, bias0);
    edge_msg_kernel<<<msg_blocks, 256>>>(0);

    // ---- conv1 ----
    gemm_fused_kernel<64, 1><<<gemm_grid, 256, smem64>>>(nullptr, bias0);
    edge_msg_kernel<<<msg_blocks, 256>>>(1);

    // ---- conv2 ----
    gemm_fused_kernel<64, 2><<<gemm_grid, 256, smem64>>>(nullptr, bias1);
    edge_msg_kernel<<<msg_blocks, 256>>>(2);

    // ---- pool (fused final combine) + head ----
    pool_kernel<<<(NN + 31) / 32, 256>>>(batch, bias2);
    head_kernel<<<NG, 64>>>(lin0_w, lin0_b, lin1_w, lin1_b, out);
}

// round 10
// speedup vs baseline: 1.2167x; 1.1125x over previous
#include <cuda_runtime.h>
#include <cuda_bf16.h>
#include <cstdint>

#define NN      10000
#define EE      30000
#define FEDGE   8
#define EMB     64
#define HID     16
#define NG      64
#define NCOL    1088   // 1024 P | 64 Q
#define QOFF    1024

// ---------------- scratch (device globals) --------------------------------
__device__ __align__(128) float g_h0[EE * HID];
__device__ __align__(128) float g_h1[EE * HID];
__device__ __align__(128) float g_PQ[(size_t)NN * NCOL];
__device__ __align__(128) float g_agg0[NN * EMB];
__device__ __align__(128) float g_agg1[NN * EMB];
__device__ __align__(128) float g_agg2[NN * EMB];
__device__ __align__(128) float g_xr0[NN * EMB];
__device__ __align__(128) float g_xr1[NN * EMB];
__device__ __align__(128) float g_xr2[NN * EMB];
__device__ __align__(128) float g_WT0[NCOL * 32];  // [c][i] P+Q, conv0
__device__ __align__(128) float g_WT1[NCOL * 64];  // [c][i] P+Q, convs 1&2
__device__ __align__(128) float g_RT0[64 * 32];    // [o][i] rootT
__device__ __align__(128) float g_RT1[64 * 64];
__device__ __align__(128) float g_RT2[64 * 64];
__device__ __align__(128) float g_pool[NG * EMB];

// ---------------- helpers --------------------------------------------------
__device__ __forceinline__ uint32_t smem_u32(const void* p) {
    uint32_t a;
    asm("{ .reg .u64 t; cvta.to.shared.u64 t, %1; cvt.u32.u64 %0, t; }" : "=r"(a) : "l"(p));
    return a;
}
__device__ __forceinline__ void ldmx4(uint32_t* r, uint32_t addr) {
    asm volatile("ldmatrix.sync.aligned.m8n8.x4.shared.b16 {%0,%1,%2,%3}, [%4];"
        : "=r"(r[0]), "=r"(r[1]), "=r"(r[2]), "=r"(r[3]) : "r"(addr));
}
__device__ __forceinline__ void mma_bf16(float* d, const uint32_t* a,
                                         uint32_t b0, uint32_t b1) {
    asm volatile("mma.sync.aligned.m16n8k16.row.col.f32.bf16.bf16.f32 "
        "{%0,%1,%2,%3}, {%4,%5,%6,%7}, {%8,%9}, {%0,%1,%2,%3};"
        : "+f"(d[0]), "+f"(d[1]), "+f"(d[2]), "+f"(d[3])
        : "r"(a[0]), "r"(a[1]), "r"(a[2]), "r"(a[3]), "r"(b0), "r"(b1));
}
__device__ __forceinline__ void split_pack(float fx, float fy,
                                           uint32_t& hi, uint32_t& lo) {
    __nv_bfloat16 hx = __float2bfloat16(fx), hy = __float2bfloat16(fy);
    hi = ((uint32_t)__bfloat16_as_ushort(hy) << 16) | __bfloat16_as_ushort(hx);
    __nv_bfloat16 lx = __float2bfloat16(fx - __bfloat162float(hx));
    __nv_bfloat16 ly = __float2bfloat16(fy - __bfloat162float(hy));
    lo = ((uint32_t)__bfloat16_as_ushort(ly) << 16) | __bfloat16_as_ushort(lx);
}

// ---------------- prep: transposes + edge MLP hiddens ----------------------
#define TR_BLOCKS 37
#define EH_BLOCKS ((EE + 255) / 256)

__global__ __launch_bounds__(256) void prep_kernel(
    const float* __restrict__ ea,
    const float* __restrict__ nn0_w1, const float* __restrict__ nn0_b1,
    const float* __restrict__ nn0_w2, const float* __restrict__ nn0_b2,
    const float* __restrict__ nn1_w1, const float* __restrict__ nn1_b1,
    const float* __restrict__ nn1_w2, const float* __restrict__ nn1_b2,
    const float* __restrict__ root0, const float* __restrict__ root1,
    const float* __restrict__ root2)
{
    int tid = threadIdx.x;
    int b = blockIdx.x;

    if (b < TR_BLOCKS) {
        __shared__ float ts[64 * 65];
        const float* src;
        float* dst;
        int D;
        if (b < 17)       { D = 32; src = (b < 16) ? nn0_w2 + b * 2048 : nn0_b2;
                            dst = g_WT0 + b * 64 * 32; }
        else if (b == 17) { D = 32; src = root0; dst = g_RT0; }
        else if (b < 35)  { int bb = b - 18; D = 64;
                            src = (bb < 16) ? nn1_w2 + bb * 4096 : nn1_b2;
                            dst = g_WT1 + bb * 64 * 64; }
        else if (b == 35) { D = 64; src = root1; dst = g_RT1; }
        else              { D = 64; src = root2; dst = g_RT2; }

        for (int idx = tid; idx < 64 * D; idx += 256) {
            int o = idx & 63, i = idx >> 6;
            ts[o * 65 + i] = src[i * 64 + o];
        }
        __syncthreads();
        for (int idx = tid; idx < 64 * D; idx += 256) {
            int i = idx & (D - 1), o = idx / D;
            dst[idx] = ts[o * 65 + i];
        }
        return;
    }

    __shared__ float sw0[FEDGE * HID], sw1[FEDGE * HID];
    __shared__ float sb0[HID], sb1[HID];
    if (tid < FEDGE * HID) { sw0[tid] = nn0_w1[tid]; sw1[tid] = nn1_w1[tid]; }
    if (tid < HID)         { sb0[tid] = nn0_b1[tid]; sb1[tid] = nn1_b1[tid]; }
    __syncthreads();

    int e = (b - TR_BLOCKS) * 256 + tid;
    if (e >= EE) return;
    const float4* p = reinterpret_cast<const float4*>(ea + (size_t)e * FEDGE);
    float4 v0 = p[0], v1 = p[1];
    float a[8] = {v0.x, v0.y, v0.z, v0.w, v1.x, v1.y, v1.z, v1.w};
#pragma unroll
    for (int h = 0; h < HID; h++) {
        float s0 = sb0[h], s1 = sb1[h];
#pragma unroll
        for (int j = 0; j < FEDGE; j++) {
            s0 += a[j] * sw0[j * HID + h];
            s1 += a[j] * sw1[j * HID + h];
        }
        g_h0[e * HID + h] = fmaxf(s0, 0.f);
        g_h1[e * HID + h] = fmaxf(s1, 0.f);
    }
}

// ---------------- fused HMMA GEMM (single-barrier variant) -----------------
// [x | relu(agg+xr+bias)] (128 rows) @ WT^T, 2 column tiles per block.
// Both B tiles staged into separate buffers + A staged, ONE __syncthreads,
// then per-tile compute with 32-reg accumulators. Tiles 0..16 -> g_PQ,
// tile 17 -> g_xr (root product). Also zeroes the next conv's agg.
template <int D, int MODE>
__global__ __launch_bounds__(256, 2) void gemm_fused_kernel(
    const float* __restrict__ xin, const float* __restrict__ biasin)
{
    const int SD = D + 8;
    const int CPT = D / 8;
    extern __shared__ ushort smu[];
    ushort* Ah = smu;                    // 128*SD
    ushort* Al = Ah + 128 * SD;
    ushort* Bh = Al + 128 * SD;          // 2 tiles x 64*SD
    ushort* Bl = Bh + 2 * 64 * SD;

    const float* __restrict__ aggin = (MODE == 1) ? g_agg0 : g_agg1;
    const float* __restrict__ xrin  = (MODE == 1) ? g_xr0  : g_xr1;
    float* __restrict__ aggz  = (MODE == 0) ? g_agg0 : (MODE == 1 ? g_agg1 : g_agg2);
    float* __restrict__ xrout = (MODE == 0) ? g_xr0  : (MODE == 1 ? g_xr1  : g_xr2);
    const float* __restrict__ WT = (MODE == 0) ? g_WT0 : g_WT1;
    const float* __restrict__ RT = (MODE == 0) ? g_RT0 : (MODE == 1 ? g_RT1 : g_RT2);

    int tid = threadIdx.x, wid = tid >> 5, l = tid & 31;
    int wm = wid & 3, wn = wid >> 2;
    int m0 = blockIdx.y * 128;
    int t0 = blockIdx.x * 2;

    // zero next agg buffer (consumed by the following edge_msg launch)
    {
        int nthr = gridDim.x * gridDim.y * 256;
        for (int i = (blockIdx.y * gridDim.x + blockIdx.x) * 256 + tid;
             i < NN * EMB; i += nthr)
            aggz[i] = 0.f;
    }

    // ---- stage BOTH B tiles ----
#pragma unroll
    for (int ti = 0; ti < 2; ti++) {
        int ct = t0 + ti;
        const float* __restrict__ bsrc = (ct == 17) ? RT : WT + (size_t)ct * 64 * D;
        for (int idx = tid; idx < 64 * CPT; idx += 256) {
            int r = idx / CPT, cb = (idx % CPT) * 8;
            float4 b0 = *reinterpret_cast<const float4*>(bsrc + r * D + cb);
            float4 b1 = *reinterpret_cast<const float4*>(bsrc + r * D + cb + 4);
            float bv[8] = {b0.x,b0.y,b0.z,b0.w,b1.x,b1.y,b1.z,b1.w};
            uint32_t* bh32 = reinterpret_cast<uint32_t*>(Bh + ti * 64 * SD);
            uint32_t* bl32 = reinterpret_cast<uint32_t*>(Bl + ti * 64 * SD);
            int base = (r * SD + cb) >> 1;
#pragma unroll
            for (int j = 0; j < 4; j++) {
                uint32_t hi, lo;
                split_pack(bv[2*j], bv[2*j+1], hi, lo);
                bh32[base + j] = hi;
                bl32[base + j] = lo;
            }
        }
    }

    // ---- stage A once (full D), fp32 -> bf16 hi/lo; bias via __ldg -------
    for (int idx = tid; idx < 128 * CPT; idx += 256) {
        int r = idx / CPT, cb = (idx % CPT) * 8;
        int n = m0 + r;
        bool v = (n < NN);
        float vals[8];
        if (MODE == 0) {
            float4 a0 = make_float4(0.f, 0.f, 0.f, 0.f), a1 = a0;
            if (v) {
                a0 = *reinterpret_cast<const float4*>(xin + (size_t)n * D + cb);
                a1 = *reinterpret_cast<const float4*>(xin + (size_t)n * D + cb + 4);
            }
            vals[0]=a0.x; vals[1]=a0.y; vals[2]=a0.z; vals[3]=a0.w;
            vals[4]=a1.x; vals[5]=a1.y; vals[6]=a1.z; vals[7]=a1.w;
        } else {
            float4 bi0 = __ldg(reinterpret_cast<const float4*>(biasin + cb));
            float4 bi1 = __ldg(reinterpret_cast<const float4*>(biasin + cb + 4));
            float4 g0 = make_float4(0.f,0.f,0.f,0.f), g1 = g0, r0 = g0, r1 = g0;
            if (v) {
                g0 = *reinterpret_cast<const float4*>(aggin + (size_t)n * EMB + cb);
                g1 = *reinterpret_cast<const float4*>(aggin + (size_t)n * EMB + cb + 4);
                r0 = *reinterpret_cast<const float4*>(xrin + (size_t)n * EMB + cb);
                r1 = *reinterpret_cast<const float4*>(xrin + (size_t)n * EMB + cb + 4);
            }
            vals[0] = fmaxf(g0.x + r0.x + bi0.x, 0.f);
            vals[1] = fmaxf(g0.y + r0.y + bi0.y, 0.f);
            vals[2] = fmaxf(g0.z + r0.z + bi0.z, 0.f);
            vals[3] = fmaxf(g0.w + r0.w + bi0.w, 0.f);
            vals[4] = fmaxf(g1.x + r1.x + bi1.x, 0.f);
            vals[5] = fmaxf(g1.y + r1.y + bi1.y, 0.f);
            vals[6] = fmaxf(g1.z + r1.z + bi1.z, 0.f);
            vals[7] = fmaxf(g1.w + r1.w + bi1.w, 0.f);
        }
        uint32_t* ah32 = reinterpret_cast<uint32_t*>(Ah);
        uint32_t* al32 = reinterpret_cast<uint32_t*>(Al);
        int base = (r * SD + cb) >> 1;
#pragma unroll
        for (int j = 0; j < 4; j++) {
            uint32_t hi, lo;
            split_pack(vals[2*j], vals[2*j+1], hi, lo);
            ah32[base + j] = hi;
            al32[base + j] = lo;
        }
    }
    __syncthreads();      // the only barrier

    uint32_t aAh = smem_u32(Ah), aAl = smem_u32(Al);
    uint32_t aBh = smem_u32(Bh), aBl = smem_u32(Bl);

#pragma unroll
    for (int ti = 0; ti < 2; ti++) {
        int ct = t0 + ti;

        float acc[2][4][4];
#pragma unroll
        for (int mi = 0; mi < 2; mi++)
#pragma unroll
            for (int nf = 0; nf < 4; nf++)
#pragma unroll
                for (int q = 0; q < 4; q++) acc[mi][nf][q] = 0.f;

#pragma unroll
        for (int ks = 0; ks < D; ks += 16) {
            uint32_t ahf[2][4], alf[2][4];
#pragma unroll
            for (int mi = 0; mi < 2; mi++) {
                uint32_t off = ((uint32_t)(wm * 32 + mi * 16 + (l & 15)) * SD
                                + ks + (l >> 4) * 8) * 2;
                ldmx4(ahf[mi], aAh + off);
                ldmx4(alf[mi], aAl + off);
            }
            uint32_t bhf[8], blf[8];
#pragma unroll
            for (int g = 0; g < 2; g++) {
                uint32_t off = (uint32_t)(ti * 64 * SD) * 2
                    + ((uint32_t)(wn * 32 + g * 16 + (l & 7) + ((l >> 4) & 1) * 8) * SD
                       + ks + ((l >> 3) & 1) * 8) * 2;
                ldmx4(bhf + g * 4, aBh + off);
                ldmx4(blf + g * 4, aBl + off);
            }
#pragma unroll
            for (int mi = 0; mi < 2; mi++)
#pragma unroll
                for (int nf = 0; nf < 4; nf++) {
                    mma_bf16(acc[mi][nf], ahf[mi], bhf[nf*2], bhf[nf*2+1]);
                    mma_bf16(acc[mi][nf], alf[mi], bhf[nf*2], bhf[nf*2+1]);
                    mma_bf16(acc[mi][nf], ahf[mi], blf[nf*2], blf[nf*2+1]);
                }
        }

        // ---- writeback ----
#pragma unroll
        for (int mi = 0; mi < 2; mi++)
#pragma unroll
            for (int nf = 0; nf < 4; nf++) {
                int gr = m0 + wm * 32 + mi * 16 + (l >> 2);
                int co = ct * 64 + wn * 32 + nf * 8 + 2 * (l & 3);
                float2 v0 = make_float2(acc[mi][nf][0], acc[mi][nf][1]);
                float2 v1 = make_float2(acc[mi][nf][2], acc[mi][nf][3]);
                if (ct < 17) {
                    if (gr < NN)
                        *reinterpret_cast<float2*>(g_PQ + (size_t)gr * NCOL + co) = v0;
                    if (gr + 8 < NN)
                        *reinterpret_cast<float2*>(g_PQ + (size_t)(gr + 8) * NCOL + co) = v1;
                } else {
                    int cr = co - NCOL;
                    if (gr < NN)
                        *reinterpret_cast<float2*>(xrout + (size_t)gr * EMB + cr) = v0;
                    if (gr + 8 < NN)
                        *reinterpret_cast<float2*>(xrout + (size_t)(gr + 8) * EMB + cr) = v1;
                }
            }
    }
}

// ---------------- per-edge message + scatter (2 edges/warp, vec) ----------
__global__ __launch_bounds__(256) void edge_msg_kernel(const int* __restrict__ ei, int conv)
{
    int gw   = (blockIdx.x * 256 + threadIdx.x) >> 5;
    int lane = threadIdx.x & 31;
    int e    = gw * 2 + (lane >> 4);
    int sub  = lane & 15;
    if (e >= EE) return;

    const float* __restrict__ hsrc = conv ? g_h1 : g_h0;
    float* __restrict__ agg = (conv == 0) ? g_agg0 : (conv == 1 ? g_agg1 : g_agg2);

    int src = ei[e];
    int dst = ei[EE + e];
    float hv = hsrc[(size_t)e * HID + sub];

    const float* __restrict__ P = g_PQ + (size_t)src * NCOL;
    float4 acc = *reinterpret_cast<const float4*>(P + QOFF + sub * 4);
#pragma unroll
    for (int h = 0; h < HID; h++) {
        float w = __shfl_sync(0xffffffffu, hv, (lane & 16) | h);
        float4 f = *reinterpret_cast<const float4*>(P + h * EMB + sub * 4);
        acc.x += w * f.x; acc.y += w * f.y; acc.z += w * f.z; acc.w += w * f.w;
    }
    float* a = agg + (size_t)dst * EMB + sub * 4;
    asm volatile("red.global.add.v4.f32 [%0], {%1,%2,%3,%4};"
                 :: "l"(a), "f"(acc.x), "f"(acc.y), "f"(acc.z), "f"(acc.w)
                 : "memory");
}

// ---------------- pool (fused final combine; batch sorted, x >= 0) --------
__global__ __launch_bounds__(256) void pool_kernel(const int* __restrict__ batch,
                                                   const float* __restrict__ bias2)
{
    int tid = threadIdx.x;
    int o = tid & 63, seg = tid >> 6;
    int n0 = blockIdx.x * 32 + seg * 8;
    float bz = __ldg(bias2 + o);
    int curb = -1;
    float m = 0.f;
    for (int k = 0; k < 8; k++) {
        int n = n0 + k;
        if (n >= NN) break;
        int b = batch[n];
        if (b != curb) {
            if (curb >= 0)
                atomicMax(reinterpret_cast<unsigned*>(g_pool + (size_t)curb * EMB + o),
                          __float_as_uint(m));
            curb = b;
            m = 0.f;
        }
        float x = fmaxf(g_agg2[(size_t)n * EMB + o] + g_xr2[(size_t)n * EMB + o] + bz, 0.f);
        m = fmaxf(m, x);
    }
    if (curb >= 0)
        atomicMax(reinterpret_cast<unsigned*>(g_pool + (size_t)curb * EMB + o),
                  __float_as_uint(m));
}

// ---------------- head -----------------------------------------------------
__global__ __launch_bounds__(64) void head_kernel(
    const float* __restrict__ lin0w, const float* __restrict__ lin0b,
    const float* __restrict__ lin1w, const float* __restrict__ lin1b,
    float* __restrict__ out)
{
    __shared__ float pg[EMB];
    __shared__ float red[EMB];
    int g = blockIdx.x, o = threadIdx.x;
    pg[o] = g_pool[(size_t)g * EMB + o];
    __syncthreads();

    float h = lin0b[o];
#pragma unroll
    for (int i = 0; i < EMB; i++) h += pg[i] * lin0w[i * EMB + o];
    red[o] = h * lin1w[o];
    __syncthreads();
#pragma unroll
    for (int s = 32; s > 0; s >>= 1) {
        if (o < s) red[o] += red[o + s];
        __syncthreads();
    }
    if (o == 0) out[g] = red[0] + lin1b[0];
}

// ---------------- launch ----------------------------------------------------
extern "C" void kernel_launch(void* const* d_in, const int* in_sizes, int n_in,
                              void* d_out, int out_size)
{
    const float* x_p    = (const float*)d_in[0];
    const float* ea     = (const float*)d_in[2];
    const int*   ei     = (const int*)  d_in[4];
    const int*   batch  = (const int*)  d_in[5];
    const float* nn0_w1 = (const float*)d_in[6];
    const float* nn0_b1 = (const float*)d_in[7];
    const float* nn0_w2 = (const float*)d_in[8];
    const float* nn0_b2 = (const float*)d_in[9];
    const float* nn1_w1 = (const float*)d_in[10];
    const float* nn1_b1 = (const float*)d_in[11];
    const float* nn1_w2 = (const float*)d_in[12];
    const float* nn1_b2 = (const float*)d_in[13];
    const float* root0  = (const float*)d_in[14];
    const float* bias0  = (const float*)d_in[15];
    const float* root1  = (const float*)d_in[16];
    const float* bias1  = (const float*)d_in[17];
    const float* root2  = (const float*)d_in[18];
    const float* bias2  = (const float*)d_in[19];
    const float* lin0_w = (const float*)d_in[20];
    const float* lin0_b = (const float*)d_in[21];
    const float* lin1_w = (const float*)d_in[22];
    const float* lin1_b = (const float*)d_in[23];
    float* out = (float*)d_out;

    // smem: A 128*SD*4 + B 2*64*SD*4 bytes
    int smem32 = 128 * 40 * 4 + 2 * 64 * 40 * 4;   // 40960
    int smem64 = 128 * 72 * 4 + 2 * 64 * 72 * 4;   // 73728

    static bool attr_done = false;
    if (!attr_done) {
        cudaFuncSetAttribute(gemm_fused_kernel<64, 1>,
                             cudaFuncAttributeMaxDynamicSharedMemorySize, smem64);
        cudaFuncSetAttribute(gemm_fused_kernel<64, 2>,
                             cudaFuncAttributeMaxDynamicSharedMemorySize, smem64);
        attr_done = true;
    }

    dim3 gemm_grid(9, (NN + 127) / 128);
    int msg_blocks = EE / 16;

    prep_kernel<<<TR_BLOCKS + EH_BLOCKS, 256>>>(
        ea, nn0_w1, nn0_b1, nn0_w2, nn0_b2, nn1_w1, nn1_b1, nn1_w2, nn1_b2,
        root0, root1, root2);

    // ---- conv0 ----
    gemm_fused_kernel<32, 0><<<gemm_grid, 256, smem32>>>(x_p, bias0);
    edge_msg_kernel<<<msg_blocks, 256>>>(ei, 0);

    // ---- conv1 ----
    gemm_fused_kernel<64, 1><<<gemm_grid, 256, smem64>>>(nullptr, bias0);
    edge_msg_kernel<<<msg_blocks, 256>>>(ei, 1);

    // ---- conv2 ----
    gemm_fused_kernel<64, 2><<<gemm_grid, 256, smem64>>>(nullptr, bias1);
    edge_msg_kernel<<<msg_blocks, 256>>>(ei, 2);

    // ---- pool (fused final combine) + head ----
    pool_kernel<<<(NN + 31) / 32, 256>>>(batch, bias2);
    head_kernel<<<NG, 64>>>(lin0_w, lin0_b, lin1_w, lin1_b, out);
}

// round 11
// speedup vs baseline: 1.2198x; 1.0026x over previous
#include <cuda_runtime.h>
#include <cuda_bf16.h>
#include <cstdint>

#define NN      10000
#define EE      30000
#define FEDGE   8
#define EMB     64
#define HID     16
#define NG      64
#define NCOL    1088   // 1024 P | 64 Q
#define QOFF    1024

// ---------------- scratch (device globals) --------------------------------
__device__ __align__(128) float g_h0[EE * HID];
__device__ __align__(128) float g_h1[EE * HID];
__device__ __align__(128) float g_PQ[(size_t)NN * NCOL];
// agg buffers double as root-product init: gemm tile-17 writes x@root into
// the NEXT conv's agg, edge_msg accumulates messages on top.
__device__ __align__(128) float g_agg0[NN * EMB];
__device__ __align__(128) float g_agg1[NN * EMB];
__device__ __align__(128) float g_agg2[NN * EMB];
__device__ __align__(128) float g_WT0[NCOL * 32];  // [c][i] P+Q, conv0
__device__ __align__(128) float g_WT1[NCOL * 64];  // [c][i] P+Q, convs 1&2
__device__ __align__(128) float g_RT0[64 * 32];    // [o][i] rootT
__device__ __align__(128) float g_RT1[64 * 64];
__device__ __align__(128) float g_RT2[64 * 64];
__device__ __align__(128) float g_pool[NG * EMB];

// ---------------- helpers --------------------------------------------------
__device__ __forceinline__ uint32_t smem_u32(const void* p) {
    uint32_t a;
    asm("{ .reg .u64 t; cvta.to.shared.u64 t, %1; cvt.u32.u64 %0, t; }" : "=r"(a) : "l"(p));
    return a;
}
__device__ __forceinline__ void ldmx4(uint32_t* r, uint32_t addr) {
    asm volatile("ldmatrix.sync.aligned.m8n8.x4.shared.b16 {%0,%1,%2,%3}, [%4];"
        : "=r"(r[0]), "=r"(r[1]), "=r"(r[2]), "=r"(r[3]) : "r"(addr));
}
__device__ __forceinline__ void mma_bf16(float* d, const uint32_t* a,
                                         uint32_t b0, uint32_t b1) {
    asm volatile("mma.sync.aligned.m16n8k16.row.col.f32.bf16.bf16.f32 "
        "{%0,%1,%2,%3}, {%4,%5,%6,%7}, {%8,%9}, {%0,%1,%2,%3};"
        : "+f"(d[0]), "+f"(d[1]), "+f"(d[2]), "+f"(d[3])
        : "r"(a[0]), "r"(a[1]), "r"(a[2]), "r"(a[3]), "r"(b0), "r"(b1));
}
__device__ __forceinline__ void split_pack(float fx, float fy,
                                           uint32_t& hi, uint32_t& lo) {
    __nv_bfloat16 hx = __float2bfloat16(fx), hy = __float2bfloat16(fy);
    hi = ((uint32_t)__bfloat16_as_ushort(hy) << 16) | __bfloat16_as_ushort(hx);
    __nv_bfloat16 lx = __float2bfloat16(fx - __bfloat162float(hx));
    __nv_bfloat16 ly = __float2bfloat16(fy - __bfloat162float(hy));
    lo = ((uint32_t)__bfloat16_as_ushort(ly) << 16) | __bfloat16_as_ushort(lx);
}

// ---------------- prep: transposes + edge MLP hiddens ----------------------
#define TR_BLOCKS 37
#define EH_BLOCKS ((EE + 255) / 256)

__global__ __launch_bounds__(256) void prep_kernel(
    const float* __restrict__ ea,
    const float* __restrict__ nn0_w1, const float* __restrict__ nn0_b1,
    const float* __restrict__ nn0_w2, const float* __restrict__ nn0_b2,
    const float* __restrict__ nn1_w1, const float* __restrict__ nn1_b1,
    const float* __restrict__ nn1_w2, const float* __restrict__ nn1_b2,
    const float* __restrict__ root0, const float* __restrict__ root1,
    const float* __restrict__ root2)
{
    int tid = threadIdx.x;
    int b = blockIdx.x;

    if (b < TR_BLOCKS) {
        __shared__ float ts[64 * 65];
        const float* src;
        float* dst;
        int D;
        if (b < 17)       { D = 32; src = (b < 16) ? nn0_w2 + b * 2048 : nn0_b2;
                            dst = g_WT0 + b * 64 * 32; }
        else if (b == 17) { D = 32; src = root0; dst = g_RT0; }
        else if (b < 35)  { int bb = b - 18; D = 64;
                            src = (bb < 16) ? nn1_w2 + bb * 4096 : nn1_b2;
                            dst = g_WT1 + bb * 64 * 64; }
        else if (b == 35) { D = 64; src = root1; dst = g_RT1; }
        else              { D = 64; src = root2; dst = g_RT2; }

        for (int idx = tid; idx < 64 * D; idx += 256) {
            int o = idx & 63, i = idx >> 6;
            ts[o * 65 + i] = src[i * 64 + o];
        }
        __syncthreads();
        for (int idx = tid; idx < 64 * D; idx += 256) {
            int i = idx & (D - 1), o = idx / D;
            dst[idx] = ts[o * 65 + i];
        }
        return;
    }

    __shared__ float sw0[FEDGE * HID], sw1[FEDGE * HID];
    __shared__ float sb0[HID], sb1[HID];
    if (tid < FEDGE * HID) { sw0[tid] = nn0_w1[tid]; sw1[tid] = nn1_w1[tid]; }
    if (tid < HID)         { sb0[tid] = nn0_b1[tid]; sb1[tid] = nn1_b1[tid]; }
    __syncthreads();

    int e = (b - TR_BLOCKS) * 256 + tid;
    if (e >= EE) return;
    const float4* p = reinterpret_cast<const float4*>(ea + (size_t)e * FEDGE);
    float4 v0 = p[0], v1 = p[1];
    float a[8] = {v0.x, v0.y, v0.z, v0.w, v1.x, v1.y, v1.z, v1.w};
#pragma unroll
    for (int h = 0; h < HID; h++) {
        float s0 = sb0[h], s1 = sb1[h];
#pragma unroll
        for (int j = 0; j < FEDGE; j++) {
            s0 += a[j] * sw0[j * HID + h];
            s1 += a[j] * sw1[j * HID + h];
        }
        g_h0[e * HID + h] = fmaxf(s0, 0.f);
        g_h1[e * HID + h] = fmaxf(s1, 0.f);
    }
}

// ---------------- fused HMMA GEMM (R5 structure; xr -> agg init) ----------
// A = [x | relu(agg+bias)] (128 rows), B = WT^T, 2 column tiles per block.
// Tiles 0..16 -> g_PQ, tile 17 (root product) -> NEXT conv's agg buffer
// (serves as its initialization; no separate zero pass, no xr buffers).
template <int D, int MODE>
__global__ __launch_bounds__(256, 2) void gemm_fused_kernel(
    const float* __restrict__ xin, const float* __restrict__ biasin)
{
    const int SD = D + 8;
    const int CPT = D / 8;
    extern __shared__ ushort smu[];
    ushort* Ah = smu;
    ushort* Al = Ah + 128 * SD;
    ushort* Bh = Al + 128 * SD;
    ushort* Bl = Bh + 64 * SD;
    __shared__ float sbias[64];

    const float* __restrict__ aggin = (MODE == 1) ? g_agg0 : g_agg1;
    float* __restrict__ aggout = (MODE == 0) ? g_agg0 : (MODE == 1 ? g_agg1 : g_agg2);
    const float* __restrict__ WT = (MODE == 0) ? g_WT0 : g_WT1;
    const float* __restrict__ RT = (MODE == 0) ? g_RT0 : (MODE == 1 ? g_RT1 : g_RT2);

    int tid = threadIdx.x, wid = tid >> 5, l = tid & 31;
    int wm = wid & 3, wn = wid >> 2;
    int m0 = blockIdx.y * 128;
    int t0 = blockIdx.x * 2;

    if (MODE && tid < 64) sbias[tid] = biasin[tid];
    if (MODE) __syncthreads();

    // ---- stage A once (full D), fp32 -> bf16 hi/lo ----
    for (int idx = tid; idx < 128 * CPT; idx += 256) {
        int r = idx / CPT, cb = (idx % CPT) * 8;
        int n = m0 + r;
        bool v = (n < NN);
        float vals[8];
        if (MODE == 0) {
            float4 a0 = make_float4(0.f, 0.f, 0.f, 0.f), a1 = a0;
            if (v) {
                a0 = *reinterpret_cast<const float4*>(xin + (size_t)n * D + cb);
                a1 = *reinterpret_cast<const float4*>(xin + (size_t)n * D + cb + 4);
            }
            vals[0]=a0.x; vals[1]=a0.y; vals[2]=a0.z; vals[3]=a0.w;
            vals[4]=a1.x; vals[5]=a1.y; vals[6]=a1.z; vals[7]=a1.w;
        } else {
            float4 g0 = make_float4(0.f,0.f,0.f,0.f), g1 = g0;
            if (v) {
                g0 = *reinterpret_cast<const float4*>(aggin + (size_t)n * EMB + cb);
                g1 = *reinterpret_cast<const float4*>(aggin + (size_t)n * EMB + cb + 4);
            }
            vals[0] = fmaxf(g0.x + sbias[cb+0], 0.f);
            vals[1] = fmaxf(g0.y + sbias[cb+1], 0.f);
            vals[2] = fmaxf(g0.z + sbias[cb+2], 0.f);
            vals[3] = fmaxf(g0.w + sbias[cb+3], 0.f);
            vals[4] = fmaxf(g1.x + sbias[cb+4], 0.f);
            vals[5] = fmaxf(g1.y + sbias[cb+5], 0.f);
            vals[6] = fmaxf(g1.z + sbias[cb+6], 0.f);
            vals[7] = fmaxf(g1.w + sbias[cb+7], 0.f);
        }
        uint32_t* ah32 = reinterpret_cast<uint32_t*>(Ah);
        uint32_t* al32 = reinterpret_cast<uint32_t*>(Al);
        int base = (r * SD + cb) >> 1;
#pragma unroll
        for (int j = 0; j < 4; j++) {
            uint32_t hi, lo;
            split_pack(vals[2*j], vals[2*j+1], hi, lo);
            ah32[base + j] = hi;
            al32[base + j] = lo;
        }
    }

    uint32_t aAh = smem_u32(Ah), aAl = smem_u32(Al);
    uint32_t aBh = smem_u32(Bh), aBl = smem_u32(Bl);

#pragma unroll
    for (int ti = 0; ti < 2; ti++) {
        int ct = t0 + ti;
        const float* __restrict__ bsrc = (ct == 17) ? RT : WT + (size_t)ct * 64 * D;

        // ---- stage B tile ----
        for (int idx = tid; idx < 64 * CPT; idx += 256) {
            int r = idx / CPT, cb = (idx % CPT) * 8;
            float4 b0 = *reinterpret_cast<const float4*>(bsrc + r * D + cb);
            float4 b1 = *reinterpret_cast<const float4*>(bsrc + r * D + cb + 4);
            float bv[8] = {b0.x,b0.y,b0.z,b0.w,b1.x,b1.y,b1.z,b1.w};
            uint32_t* bh32 = reinterpret_cast<uint32_t*>(Bh);
            uint32_t* bl32 = reinterpret_cast<uint32_t*>(Bl);
            int base = (r * SD + cb) >> 1;
#pragma unroll
            for (int j = 0; j < 4; j++) {
                uint32_t hi, lo;
                split_pack(bv[2*j], bv[2*j+1], hi, lo);
                bh32[base + j] = hi;
                bl32[base + j] = lo;
            }
        }
        __syncthreads();   // covers A-stage (iter 0) + B-stage

        float acc[2][4][4];
#pragma unroll
        for (int mi = 0; mi < 2; mi++)
#pragma unroll
            for (int nf = 0; nf < 4; nf++)
#pragma unroll
                for (int q = 0; q < 4; q++) acc[mi][nf][q] = 0.f;

#pragma unroll
        for (int ks = 0; ks < D; ks += 16) {
            uint32_t ahf[2][4], alf[2][4];
#pragma unroll
            for (int mi = 0; mi < 2; mi++) {
                uint32_t off = ((uint32_t)(wm * 32 + mi * 16 + (l & 15)) * SD
                                + ks + (l >> 4) * 8) * 2;
                ldmx4(ahf[mi], aAh + off);
                ldmx4(alf[mi], aAl + off);
            }
            uint32_t bhf[8], blf[8];
#pragma unroll
            for (int g = 0; g < 2; g++) {
                uint32_t off = ((uint32_t)(wn * 32 + g * 16 + (l & 7) + ((l >> 4) & 1) * 8) * SD
                                + ks + ((l >> 3) & 1) * 8) * 2;
                ldmx4(bhf + g * 4, aBh + off);
                ldmx4(blf + g * 4, aBl + off);
            }
#pragma unroll
            for (int mi = 0; mi < 2; mi++)
#pragma unroll
                for (int nf = 0; nf < 4; nf++) {
                    mma_bf16(acc[mi][nf], ahf[mi], bhf[nf*2], bhf[nf*2+1]);
                    mma_bf16(acc[mi][nf], alf[mi], bhf[nf*2], bhf[nf*2+1]);
                    mma_bf16(acc[mi][nf], ahf[mi], blf[nf*2], blf[nf*2+1]);
                }
        }

        // ---- writeback: P,Q tiles -> g_PQ ; root tile -> next agg init ----
#pragma unroll
        for (int mi = 0; mi < 2; mi++)
#pragma unroll
            for (int nf = 0; nf < 4; nf++) {
                int gr = m0 + wm * 32 + mi * 16 + (l >> 2);
                int co = ct * 64 + wn * 32 + nf * 8 + 2 * (l & 3);
                float2 v0 = make_float2(acc[mi][nf][0], acc[mi][nf][1]);
                float2 v1 = make_float2(acc[mi][nf][2], acc[mi][nf][3]);
                if (ct < 17) {
                    if (gr < NN)
                        *reinterpret_cast<float2*>(g_PQ + (size_t)gr * NCOL + co) = v0;
                    if (gr + 8 < NN)
                        *reinterpret_cast<float2*>(g_PQ + (size_t)(gr + 8) * NCOL + co) = v1;
                } else {
                    int cr = co - NCOL;
                    if (gr < NN)
                        *reinterpret_cast<float2*>(aggout + (size_t)gr * EMB + cr) = v0;
                    if (gr + 8 < NN)
                        *reinterpret_cast<float2*>(aggout + (size_t)(gr + 8) * EMB + cr) = v1;
                }
            }
        __syncthreads();
    }
}

// ---------------- per-edge message + scatter (2 edges/warp, vec) ----------
__global__ __launch_bounds__(256) void edge_msg_kernel(const int* __restrict__ ei, int conv)
{
    int gw   = (blockIdx.x * 256 + threadIdx.x) >> 5;
    int lane = threadIdx.x & 31;
    int e    = gw * 2 + (lane >> 4);
    int sub  = lane & 15;
    if (e >= EE) return;

    const float* __restrict__ hsrc = conv ? g_h1 : g_h0;
    float* __restrict__ agg = (conv == 0) ? g_agg0 : (conv == 1 ? g_agg1 : g_agg2);

    int src = ei[e];
    int dst = ei[EE + e];
    float hv = hsrc[(size_t)e * HID + sub];

    const float* __restrict__ P = g_PQ + (size_t)src * NCOL;
    float4 acc = *reinterpret_cast<const float4*>(P + QOFF + sub * 4);
#pragma unroll
    for (int h = 0; h < HID; h++) {
        float w = __shfl_sync(0xffffffffu, hv, (lane & 16) | h);
        float4 f = *reinterpret_cast<const float4*>(P + h * EMB + sub * 4);
        acc.x += w * f.x; acc.y += w * f.y; acc.z += w * f.z; acc.w += w * f.w;
    }
    float* a = agg + (size_t)dst * EMB + sub * 4;
    asm volatile("red.global.add.v4.f32 [%0], {%1,%2,%3,%4};"
                 :: "l"(a), "f"(acc.x), "f"(acc.y), "f"(acc.z), "f"(acc.w)
                 : "memory");
}

// ---------------- pool (fused final combine; batch sorted, x >= 0) --------
__global__ __launch_bounds__(256) void pool_kernel(const int* __restrict__ batch,
                                                   const float* __restrict__ bias2)
{
    int tid = threadIdx.x;
    int o = tid & 63, seg = tid >> 6;
    int n0 = blockIdx.x * 32 + seg * 8;
    float bz = __ldg(bias2 + o);
    int curb = -1;
    float m = 0.f;
    for (int k = 0; k < 8; k++) {
        int n = n0 + k;
        if (n >= NN) break;
        int b = batch[n];
        if (b != curb) {
            if (curb >= 0)
                atomicMax(reinterpret_cast<unsigned*>(g_pool + (size_t)curb * EMB + o),
                          __float_as_uint(m));
            curb = b;
            m = 0.f;
        }
        float x = fmaxf(g_agg2[(size_t)n * EMB + o] + bz, 0.f);
        m = fmaxf(m, x);
    }
    if (curb >= 0)
        atomicMax(reinterpret_cast<unsigned*>(g_pool + (size_t)curb * EMB + o),
                  __float_as_uint(m));
}

// ---------------- head -----------------------------------------------------
__global__ __launch_bounds__(64) void head_kernel(
    const float* __restrict__ lin0w, const float* __restrict__ lin0b,
    const float* __restrict__ lin1w, const float* __restrict__ lin1b,
    float* __restrict__ out)
{
    __shared__ float pg[EMB];
    __shared__ float red[EMB];
    int g = blockIdx.x, o = threadIdx.x;
    pg[o] = g_pool[(size_t)g * EMB + o];
    __syncthreads();

    float h = lin0b[o];
#pragma unroll
    for (int i = 0; i < EMB; i++) h += pg[i] * lin0w[i * EMB + o];
    red[o] = h * lin1w[o];
    __syncthreads();
#pragma unroll
    for (int s = 32; s > 0; s >>= 1) {
        if (o < s) red[o] += red[o + s];
        __syncthreads();
    }
    if (o == 0) out[g] = red[0] + lin1b[0];
}

// ---------------- launch ----------------------------------------------------
extern "C" void kernel_launch(void* const* d_in, const int* in_sizes, int n_in,
                              void* d_out, int out_size)
{
    const float* x_p    = (const float*)d_in[0];
    const float* ea     = (const float*)d_in[2];
    const int*   ei     = (const int*)  d_in[4];
    const int*   batch  = (const int*)  d_in[5];
    const float* nn0_w1 = (const float*)d_in[6];
    const float* nn0_b1 = (const float*)d_in[7];
    const float* nn0_w2 = (const float*)d_in[8];
    const float* nn0_b2 = (const float*)d_in[9];
    const float* nn1_w1 = (const float*)d_in[10];
    const float* nn1_b1 = (const float*)d_in[11];
    const float* nn1_w2 = (const float*)d_in[12];
    const float* nn1_b2 = (const float*)d_in[13];
    const float* root0  = (const float*)d_in[14];
    const float* bias0  = (const float*)d_in[15];
    const float* root1  = (const float*)d_in[16];
    const float* bias1  = (const float*)d_in[17];
    const float* root2  = (const float*)d_in[18];
    const float* bias2  = (const float*)d_in[19];
    const float* lin0_w = (const float*)d_in[20];
    const float* lin0_b = (const float*)d_in[21];
    const float* lin1_w = (const float*)d_in[22];
    const float* lin1_b = (const float*)d_in[23];
    float* out = (float*)d_out;

    int smem32 = 128 * 40 * 4 + 64 * 40 * 4;   // 30720
    int smem64 = 128 * 72 * 4 + 64 * 72 * 4;   // 55296

    static bool attr_done = false;
    if (!attr_done) {
        cudaFuncSetAttribute(gemm_fused_kernel<64, 1>,
                             cudaFuncAttributeMaxDynamicSharedMemorySize, smem64);
        cudaFuncSetAttribute(gemm_fused_kernel<64, 2>,
                             cudaFuncAttributeMaxDynamicSharedMemorySize, smem64);
        attr_done = true;
    }

    dim3 gemm_grid(9, (NN + 127) / 128);
    int msg_blocks = EE / 16;

    prep_kernel<<<TR_BLOCKS + EH_BLOCKS, 256>>>(
        ea, nn0_w1, nn0_b1, nn0_w2, nn0_b2, nn1_w1, nn1_b1, nn1_w2, nn1_b2,
        root0, root1, root2);

    // ---- conv0 ----
    gemm_fused_kernel<32, 0><<<gemm_grid, 256, smem32>>>(x_p, bias0);
    edge_msg_kernel<<<msg_blocks, 256>>>(ei, 0);

    // ---- conv1 ----
    gemm_fused_kernel<64, 1><<<gemm_grid, 256, smem64>>>(nullptr, bias0);
    edge_msg_kernel<<<msg_blocks, 256>>>(ei, 1);

    // ---- conv2 ----
    gemm_fused_kernel<64, 2><<<gemm_grid, 256, smem64>>>(nullptr, bias1);
    edge_msg_kernel<<<msg_blocks, 256>>>(ei, 2);

    // ---- pool (fused final combine) + head ----
    pool_kernel<<<(NN + 31) / 32, 256>>>(batch, bias2);
    head_kernel<<<NG, 64>>>(lin0_w, lin0_b, lin1_w, lin1_b, out);
}

// round 12
// speedup vs baseline: 1.4251x; 1.1683x over previous
#include <cuda_runtime.h>
#include <cuda_bf16.h>
#include <cstdint>

#define NN      10000
#define EE      30000
#define FEDGE   8
#define EMB     64
#define HID     16
#define NG      64
#define NCOL    1088   // 1024 P | 64 Q
#define QOFF    1024

// ---------------- scratch (device globals) --------------------------------
__device__ __align__(128) float g_h0[EE * HID];
__device__ __align__(128) float g_h1[EE * HID];
__device__ __align__(128) float g_PQ[(size_t)NN * NCOL];
// agg buffers double as root-product init: gemm tile-17 writes x@root into
// the NEXT conv's agg, edge_msg accumulates messages on top.
__device__ __align__(128) float g_agg0[NN * EMB];
__device__ __align__(128) float g_agg1[NN * EMB];
__device__ __align__(128) float g_agg2[NN * EMB];
__device__ __align__(128) float g_WT0[NCOL * 32];  // [c][i] P+Q, conv0
__device__ __align__(128) float g_WT1[NCOL * 64];  // [c][i] P+Q, convs 1&2
__device__ __align__(128) float g_RT0[64 * 32];    // [o][i] rootT
__device__ __align__(128) float g_RT1[64 * 64];
__device__ __align__(128) float g_RT2[64 * 64];
__device__ __align__(128) float g_pool[NG * EMB];

// ---------------- helpers --------------------------------------------------
__device__ __forceinline__ uint32_t smem_u32(const void* p) {
    uint32_t a;
    asm("{ .reg .u64 t; cvta.to.shared.u64 t, %1; cvt.u32.u64 %0, t; }" : "=r"(a) : "l"(p));
    return a;
}
__device__ __forceinline__ void ldmx4(uint32_t* r, uint32_t addr) {
    asm volatile("ldmatrix.sync.aligned.m8n8.x4.shared.b16 {%0,%1,%2,%3}, [%4];"
        : "=r"(r[0]), "=r"(r[1]), "=r"(r[2]), "=r"(r[3]) : "r"(addr));
}
__device__ __forceinline__ void mma_bf16(float* d, const uint32_t* a,
                                         uint32_t b0, uint32_t b1) {
    asm volatile("mma.sync.aligned.m16n8k16.row.col.f32.bf16.bf16.f32 "
        "{%0,%1,%2,%3}, {%4,%5,%6,%7}, {%8,%9}, {%0,%1,%2,%3};"
        : "+f"(d[0]), "+f"(d[1]), "+f"(d[2]), "+f"(d[3])
        : "r"(a[0]), "r"(a[1]), "r"(a[2]), "r"(a[3]), "r"(b0), "r"(b1));
}
__device__ __forceinline__ void split_pack(float fx, float fy,
                                           uint32_t& hi, uint32_t& lo) {
    __nv_bfloat16 hx = __float2bfloat16(fx), hy = __float2bfloat16(fy);
    hi = ((uint32_t)__bfloat16_as_ushort(hy) << 16) | __bfloat16_as_ushort(hx);
    __nv_bfloat16 lx = __float2bfloat16(fx - __bfloat162float(hx));
    __nv_bfloat16 ly = __float2bfloat16(fy - __bfloat162float(hy));
    lo = ((uint32_t)__bfloat16_as_ushort(ly) << 16) | __bfloat16_as_ushort(lx);
}

// ---------------- prep: transposes + edge MLP hiddens ----------------------
#define TR_BLOCKS 37
#define EH_BLOCKS ((EE + 255) / 256)

__global__ __launch_bounds__(256) void prep_kernel(
    const float* __restrict__ ea,
    const float* __restrict__ nn0_w1, const float* __restrict__ nn0_b1,
    const float* __restrict__ nn0_w2, const float* __restrict__ nn0_b2,
    const float* __restrict__ nn1_w1, const float* __restrict__ nn1_b1,
    const float* __restrict__ nn1_w2, const float* __restrict__ nn1_b2,
    const float* __restrict__ root0, const float* __restrict__ root1,
    const float* __restrict__ root2)
{
    int tid = threadIdx.x;
    int b = blockIdx.x;

    if (b < TR_BLOCKS) {
        __shared__ float ts[64 * 65];
        const float* src;
        float* dst;
        int D;
        if (b < 17)       { D = 32; src = (b < 16) ? nn0_w2 + b * 2048 : nn0_b2;
                            dst = g_WT0 + b * 64 * 32; }
        else if (b == 17) { D = 32; src = root0; dst = g_RT0; }
        else if (b < 35)  { int bb = b - 18; D = 64;
                            src = (bb < 16) ? nn1_w2 + bb * 4096 : nn1_b2;
                            dst = g_WT1 + bb * 64 * 64; }
        else if (b == 35) { D = 64; src = root1; dst = g_RT1; }
        else              { D = 64; src = root2; dst = g_RT2; }

        for (int idx = tid; idx < 64 * D; idx += 256) {
            int o = idx & 63, i = idx >> 6;
            ts[o * 65 + i] = src[i * 64 + o];
        }
        __syncthreads();
        for (int idx = tid; idx < 64 * D; idx += 256) {
            int i = idx & (D - 1), o = idx / D;
            dst[idx] = ts[o * 65 + i];
        }
        return;
    }

    __shared__ float sw0[FEDGE * HID], sw1[FEDGE * HID];
    __shared__ float sb0[HID], sb1[HID];
    if (tid < FEDGE * HID) { sw0[tid] = nn0_w1[tid]; sw1[tid] = nn1_w1[tid]; }
    if (tid < HID)         { sb0[tid] = nn0_b1[tid]; sb1[tid] = nn1_b1[tid]; }
    __syncthreads();

    int e = (b - TR_BLOCKS) * 256 + tid;
    if (e >= EE) return;
    const float4* p = reinterpret_cast<const float4*>(ea + (size_t)e * FEDGE);
    float4 v0 = p[0], v1 = p[1];
    float a[8] = {v0.x, v0.y, v0.z, v0.w, v1.x, v1.y, v1.z, v1.w};
#pragma unroll
    for (int h = 0; h < HID; h++) {
        float s0 = sb0[h], s1 = sb1[h];
#pragma unroll
        for (int j = 0; j < FEDGE; j++) {
            s0 += a[j] * sw0[j * HID + h];
            s1 += a[j] * sw1[j * HID + h];
        }
        g_h0[e * HID + h] = fmaxf(s0, 0.f);
        g_h1[e * HID + h] = fmaxf(s1, 0.f);
    }
}

// ---------------- fused HMMA GEMM (R5 structure; xr -> agg init) ----------
// A = [x | relu(agg+bias)] (128 rows), B = WT^T, 2 column tiles per block.
// Tiles 0..16 -> g_PQ, tile 17 (root product) -> NEXT conv's agg buffer
// (serves as its initialization; no separate zero pass, no xr buffers).
// __launch_bounds__(256,3) keeps regs <= 85 so 3 CTAs/SM fit (occupancy
// cliff measured across R5/R7 vs R10/R11).
template <int D, int MODE>
__global__ __launch_bounds__(256, 3) void gemm_fused_kernel(
    const float* __restrict__ xin, const float* __restrict__ biasin)
{
    const int SD = D + 8;
    const int CPT = D / 8;
    extern __shared__ ushort smu[];
    ushort* Ah = smu;
    ushort* Al = Ah + 128 * SD;
    ushort* Bh = Al + 128 * SD;
    ushort* Bl = Bh + 64 * SD;
    __shared__ float sbias[64];

    const float* __restrict__ aggin = (MODE == 1) ? g_agg0 : g_agg1;
    float* __restrict__ aggout = (MODE == 0) ? g_agg0 : (MODE == 1 ? g_agg1 : g_agg2);
    const float* __restrict__ WT = (MODE == 0) ? g_WT0 : g_WT1;
    const float* __restrict__ RT = (MODE == 0) ? g_RT0 : (MODE == 1 ? g_RT1 : g_RT2);

    int tid = threadIdx.x, wid = tid >> 5, l = tid & 31;
    int wm = wid & 3, wn = wid >> 2;
    int m0 = blockIdx.y * 128;
    int t0 = blockIdx.x * 2;

    if (MODE && tid < 64) sbias[tid] = biasin[tid];
    if (MODE) __syncthreads();

    // ---- stage A once (full D), fp32 -> bf16 hi/lo ----
    for (int idx = tid; idx < 128 * CPT; idx += 256) {
        int r = idx / CPT, cb = (idx % CPT) * 8;
        int n = m0 + r;
        bool v = (n < NN);
        float vals[8];
        if (MODE == 0) {
            float4 a0 = make_float4(0.f, 0.f, 0.f, 0.f), a1 = a0;
            if (v) {
                a0 = *reinterpret_cast<const float4*>(xin + (size_t)n * D + cb);
                a1 = *reinterpret_cast<const float4*>(xin + (size_t)n * D + cb + 4);
            }
            vals[0]=a0.x; vals[1]=a0.y; vals[2]=a0.z; vals[3]=a0.w;
            vals[4]=a1.x; vals[5]=a1.y; vals[6]=a1.z; vals[7]=a1.w;
        } else {
            float4 g0 = make_float4(0.f,0.f,0.f,0.f), g1 = g0;
            if (v) {
                g0 = *reinterpret_cast<const float4*>(aggin + (size_t)n * EMB + cb);
                g1 = *reinterpret_cast<const float4*>(aggin + (size_t)n * EMB + cb + 4);
            }
            vals[0] = fmaxf(g0.x + sbias[cb+0], 0.f);
            vals[1] = fmaxf(g0.y + sbias[cb+1], 0.f);
            vals[2] = fmaxf(g0.z + sbias[cb+2], 0.f);
            vals[3] = fmaxf(g0.w + sbias[cb+3], 0.f);
            vals[4] = fmaxf(g1.x + sbias[cb+4], 0.f);
            vals[5] = fmaxf(g1.y + sbias[cb+5], 0.f);
            vals[6] = fmaxf(g1.z + sbias[cb+6], 0.f);
            vals[7] = fmaxf(g1.w + sbias[cb+7], 0.f);
        }
        uint32_t* ah32 = reinterpret_cast<uint32_t*>(Ah);
        uint32_t* al32 = reinterpret_cast<uint32_t*>(Al);
        int base = (r * SD + cb) >> 1;
#pragma unroll
        for (int j = 0; j < 4; j++) {
            uint32_t hi, lo;
            split_pack(vals[2*j], vals[2*j+1], hi, lo);
            ah32[base + j] = hi;
            al32[base + j] = lo;
        }
    }

    uint32_t aAh = smem_u32(Ah), aAl = smem_u32(Al);
    uint32_t aBh = smem_u32(Bh), aBl = smem_u32(Bl);

#pragma unroll
    for (int ti = 0; ti < 2; ti++) {
        int ct = t0 + ti;
        const float* __restrict__ bsrc = (ct == 17) ? RT : WT + (size_t)ct * 64 * D;

        // ---- stage B tile ----
        for (int idx = tid; idx < 64 * CPT; idx += 256) {
            int r = idx / CPT, cb = (idx % CPT) * 8;
            float4 b0 = *reinterpret_cast<const float4*>(bsrc + r * D + cb);
            float4 b1 = *reinterpret_cast<const float4*>(bsrc + r * D + cb + 4);
            float bv[8] = {b0.x,b0.y,b0.z,b0.w,b1.x,b1.y,b1.z,b1.w};
            uint32_t* bh32 = reinterpret_cast<uint32_t*>(Bh);
            uint32_t* bl32 = reinterpret_cast<uint32_t*>(Bl);
            int base = (r * SD + cb) >> 1;
#pragma unroll
            for (int j = 0; j < 4; j++) {
                uint32_t hi, lo;
                split_pack(bv[2*j], bv[2*j+1], hi, lo);
                bh32[base + j] = hi;
                bl32[base + j] = lo;
            }
        }
        __syncthreads();   // covers A-stage (iter 0) + B-stage

        float acc[2][4][4];
#pragma unroll
        for (int mi = 0; mi < 2; mi++)
#pragma unroll
            for (int nf = 0; nf < 4; nf++)
#pragma unroll
                for (int q = 0; q < 4; q++) acc[mi][nf][q] = 0.f;

#pragma unroll
        for (int ks = 0; ks < D; ks += 16) {
            uint32_t ahf[2][4], alf[2][4];
#pragma unroll
            for (int mi = 0; mi < 2; mi++) {
                uint32_t off = ((uint32_t)(wm * 32 + mi * 16 + (l & 15)) * SD
                                + ks + (l >> 4) * 8) * 2;
                ldmx4(ahf[mi], aAh + off);
                ldmx4(alf[mi], aAl + off);
            }
            uint32_t bhf[8], blf[8];
#pragma unroll
            for (int g = 0; g < 2; g++) {
                uint32_t off = ((uint32_t)(wn * 32 + g * 16 + (l & 7) + ((l >> 4) & 1) * 8) * SD
                                + ks + ((l >> 3) & 1) * 8) * 2;
                ldmx4(bhf + g * 4, aBh + off);
                ldmx4(blf + g * 4, aBl + off);
            }
#pragma unroll
            for (int mi = 0; mi < 2; mi++)
#pragma unroll
                for (int nf = 0; nf < 4; nf++) {
                    mma_bf16(acc[mi][nf], ahf[mi], bhf[nf*2], bhf[nf*2+1]);
                    mma_bf16(acc[mi][nf], alf[mi], bhf[nf*2], bhf[nf*2+1]);
                    mma_bf16(acc[mi][nf], ahf[mi], blf[nf*2], blf[nf*2+1]);
                }
        }

        // ---- writeback: P,Q tiles -> g_PQ ; root tile -> next agg init ----
#pragma unroll
        for (int mi = 0; mi < 2; mi++)
#pragma unroll
            for (int nf = 0; nf < 4; nf++) {
                int gr = m0 + wm * 32 + mi * 16 + (l >> 2);
                int co = ct * 64 + wn * 32 + nf * 8 + 2 * (l & 3);
                float2 v0 = make_float2(acc[mi][nf][0], acc[mi][nf][1]);
                float2 v1 = make_float2(acc[mi][nf][2], acc[mi][nf][3]);
                if (ct < 17) {
                    if (gr < NN)
                        *reinterpret_cast<float2*>(g_PQ + (size_t)gr * NCOL + co) = v0;
                    if (gr + 8 < NN)
                        *reinterpret_cast<float2*>(g_PQ + (size_t)(gr + 8) * NCOL + co) = v1;
                } else {
                    int cr = co - NCOL;
                    if (gr < NN)
                        *reinterpret_cast<float2*>(aggout + (size_t)gr * EMB + cr) = v0;
                    if (gr + 8 < NN)
                        *reinterpret_cast<float2*>(aggout + (size_t)(gr + 8) * EMB + cr) = v1;
                }
            }
        __syncthreads();
    }
}

// ---------------- per-edge message + scatter (2 edges/warp, vec) ----------
__global__ __launch_bounds__(256) void edge_msg_kernel(const int* __restrict__ ei, int conv)
{
    int gw   = (blockIdx.x * 256 + threadIdx.x) >> 5;
    int lane = threadIdx.x & 31;
    int e    = gw * 2 + (lane >> 4);
    int sub  = lane & 15;
    if (e >= EE) return;

    const float* __restrict__ hsrc = conv ? g_h1 : g_h0;
    float* __restrict__ agg = (conv == 0) ? g_agg0 : (conv == 1 ? g_agg1 : g_agg2);

    int src = ei[e];
    int dst = ei[EE + e];
    float hv = hsrc[(size_t)e * HID + sub];

    const float* __restrict__ P = g_PQ + (size_t)src * NCOL;
    float4 acc = *reinterpret_cast<const float4*>(P + QOFF + sub * 4);
#pragma unroll
    for (int h = 0; h < HID; h++) {
        float w = __shfl_sync(0xffffffffu, hv, (lane & 16) | h);
        float4 f = *reinterpret_cast<const float4*>(P + h * EMB + sub * 4);
        acc.x += w * f.x; acc.y += w * f.y; acc.z += w * f.z; acc.w += w * f.w;
    }
    float* a = agg + (size_t)dst * EMB + sub * 4;
    asm volatile("red.global.add.v4.f32 [%0], {%1,%2,%3,%4};"
                 :: "l"(a), "f"(acc.x), "f"(acc.y), "f"(acc.z), "f"(acc.w)
                 : "memory");
}

// ---------------- pool (fused final combine; batch sorted, x >= 0) --------
__global__ __launch_bounds__(256) void pool_kernel(const int* __restrict__ batch,
                                                   const float* __restrict__ bias2)
{
    int tid = threadIdx.x;
    int o = tid & 63, seg = tid >> 6;
    int n0 = blockIdx.x * 32 + seg * 8;
    float bz = __ldg(bias2 + o);
    int curb = -1;
    float m = 0.f;
    for (int k = 0; k < 8; k++) {
        int n = n0 + k;
        if (n >= NN) break;
        int b = batch[n];
        if (b != curb) {
            if (curb >= 0)
                atomicMax(reinterpret_cast<unsigned*>(g_pool + (size_t)curb * EMB + o),
                          __float_as_uint(m));
            curb = b;
            m = 0.f;
        }
        float x = fmaxf(g_agg2[(size_t)n * EMB + o] + bz, 0.f);
        m = fmaxf(m, x);
    }
    if (curb >= 0)
        atomicMax(reinterpret_cast<unsigned*>(g_pool + (size_t)curb * EMB + o),
                  __float_as_uint(m));
}

// ---------------- head -----------------------------------------------------
__global__ __launch_bounds__(64) void head_kernel(
    const float* __restrict__ lin0w, const float* __restrict__ lin0b,
    const float* __restrict__ lin1w, const float* __restrict__ lin1b,
    float* __restrict__ out)
{
    __shared__ float pg[EMB];
    __shared__ float red[EMB];
    int g = blockIdx.x, o = threadIdx.x;
    pg[o] = g_pool[(size_t)g * EMB + o];
    __syncthreads();

    float h = lin0b[o];
#pragma unroll
    for (int i = 0; i < EMB; i++) h += pg[i] * lin0w[i * EMB + o];
    red[o] = h * lin1w[o];
    __syncthreads();
#pragma unroll
    for (int s = 32; s > 0; s >>= 1) {
        if (o < s) red[o] += red[o + s];
        __syncthreads();
    }
    if (o == 0) out[g] = red[0] + lin1b[0];
}

// ---------------- launch ----------------------------------------------------
extern "C" void kernel_launch(void* const* d_in, const int* in_sizes, int n_in,
                              void* d_out, int out_size)
{
    const float* x_p    = (const float*)d_in[0];
    const float* ea     = (const float*)d_in[2];
    const int*   ei     = (const int*)  d_in[4];
    const int*   batch  = (const int*)  d_in[5];
    const float* nn0_w1 = (const float*)d_in[6];
    const float* nn0_b1 = (const float*)d_in[7];
    const float* nn0_w2 = (const float*)d_in[8];
    const float* nn0_b2 = (const float*)d_in[9];
    const float* nn1_w1 = (const float*)d_in[10];
    const float* nn1_b1 = (const float*)d_in[11];
    const float* nn1_w2 = (const float*)d_in[12];
    const float* nn1_b2 = (const float*)d_in[13];
    const float* root0  = (const float*)d_in[14];
    const float* bias0  = (const float*)d_in[15];
    const float* root1  = (const float*)d_in[16];
    const float* bias1  = (const float*)d_in[17];
    const float* root2  = (const float*)d_in[18];
    const float* bias2  = (const float*)d_in[19];
    const float* lin0_w = (const float*)d_in[20];
    const float* lin0_b = (const float*)d_in[21];
    const float* lin1_w = (const float*)d_in[22];
    const float* lin1_b = (const float*)d_in[23];
    float* out = (float*)d_out;

    int smem32 = 128 * 40 * 4 + 64 * 40 * 4;   // 30720
    int smem64 = 128 * 72 * 4 + 64 * 72 * 4;   // 55296

    static bool attr_done = false;
    if (!attr_done) {
        cudaFuncSetAttribute(gemm_fused_kernel<64, 1>,
                             cudaFuncAttributeMaxDynamicSharedMemorySize, smem64);
        cudaFuncSetAttribute(gemm_fused_kernel<64, 2>,
                             cudaFuncAttributeMaxDynamicSharedMemorySize, smem64);
        attr_done = true;
    }

    dim3 gemm_grid(9, (NN + 127) / 128);
    int msg_blocks = EE / 16;

    prep_kernel<<<TR_BLOCKS + EH_BLOCKS, 256>>>(
        ea, nn0_w1, nn0_b1, nn0_w2, nn0_b2, nn1_w1, nn1_b1, nn1_w2, nn1_b2,
        root0, root1, root2);

    // ---- conv0 ----
    gemm_fused_kernel<32, 0><<<gemm_grid, 256, smem32>>>(x_p, bias0);
    edge_msg_kernel<<<msg_blocks, 256>>>(ei, 0);

    // ---- conv1 ----
    gemm_fused_kernel<64, 1><<<gemm_grid, 256, smem64>>>(nullptr, bias0);
    edge_msg_kernel<<<msg_blocks, 256>>>(ei, 1);

    // ---- conv2 ----
    gemm_fused_kernel<64, 2><<<gemm_grid, 256, smem64>>>(nullptr, bias1);
    edge_msg_kernel<<<msg_blocks, 256>>>(ei, 2);

    // ---- pool (fused final combine) + head ----
    pool_kernel<<<(NN + 31) / 32, 256>>>(batch, bias2);
    head_kernel<<<NG, 64>>>(lin0_w, lin0_b, lin1_w, lin1_b, out);
}

// round 13
// speedup vs baseline: 1.4476x; 1.0158x over previous
#include <cuda_runtime.h>
#include <cuda_bf16.h>
#include <cstdint>

#define NN      10000
#define EE      30000
#define FEDGE   8
#define EMB     64
#define HID     16
#define NG      64
#define NCOL    1088   // 1024 P | 64 Q
#define QOFF    1024

// PDL: programmatic dependent launch (sm_90+ base PTX, graph-capturable)
#define GDC_WAIT()   asm volatile("griddepcontrol.wait;" ::: "memory")
#define GDC_LAUNCH() asm volatile("griddepcontrol.launch_dependents;" ::: "memory")

// ---------------- scratch (device globals) --------------------------------
__device__ __align__(128) float g_h0[EE * HID];
__device__ __align__(128) float g_h1[EE * HID];
__device__ __align__(128) float g_PQ[(size_t)NN * NCOL];
// agg buffers double as root-product init: gemm tile-17 writes x@root into
// the NEXT conv's agg, edge_msg accumulates messages on top.
__device__ __align__(128) float g_agg0[NN * EMB];
__device__ __align__(128) float g_agg1[NN * EMB];
__device__ __align__(128) float g_agg2[NN * EMB];
__device__ __align__(128) float g_WT0[NCOL * 32];  // [c][i] P+Q, conv0
__device__ __align__(128) float g_WT1[NCOL * 64];  // [c][i] P+Q, convs 1&2
__device__ __align__(128) float g_RT0[64 * 32];    // [o][i] rootT
__device__ __align__(128) float g_RT1[64 * 64];
__device__ __align__(128) float g_RT2[64 * 64];
__device__ __align__(128) float g_pool[NG * EMB];

// ---------------- helpers --------------------------------------------------
__device__ __forceinline__ uint32_t smem_u32(const void* p) {
    uint32_t a;
    asm("{ .reg .u64 t; cvta.to.shared.u64 t, %1; cvt.u32.u64 %0, t; }" : "=r"(a) : "l"(p));
    return a;
}
__device__ __forceinline__ void ldmx4(uint32_t* r, uint32_t addr) {
    asm volatile("ldmatrix.sync.aligned.m8n8.x4.shared.b16 {%0,%1,%2,%3}, [%4];"
        : "=r"(r[0]), "=r"(r[1]), "=r"(r[2]), "=r"(r[3]) : "r"(addr));
}
__device__ __forceinline__ void mma_bf16(float* d, const uint32_t* a,
                                         uint32_t b0, uint32_t b1) {
    asm volatile("mma.sync.aligned.m16n8k16.row.col.f32.bf16.bf16.f32 "
        "{%0,%1,%2,%3}, {%4,%5,%6,%7}, {%8,%9}, {%0,%1,%2,%3};"
        : "+f"(d[0]), "+f"(d[1]), "+f"(d[2]), "+f"(d[3])
        : "r"(a[0]), "r"(a[1]), "r"(a[2]), "r"(a[3]), "r"(b0), "r"(b1));
}
__device__ __forceinline__ void split_pack(float fx, float fy,
                                           uint32_t& hi, uint32_t& lo) {
    __nv_bfloat16 hx = __float2bfloat16(fx), hy = __float2bfloat16(fy);
    hi = ((uint32_t)__bfloat16_as_ushort(hy) << 16) | __bfloat16_as_ushort(hx);
    __nv_bfloat16 lx = __float2bfloat16(fx - __bfloat162float(hx));
    __nv_bfloat16 ly = __float2bfloat16(fy - __bfloat162float(hy));
    lo = ((uint32_t)__bfloat16_as_ushort(ly) << 16) | __bfloat16_as_ushort(lx);
}

// ---------------- prep: transposes + edge MLP hiddens ----------------------
#define TR_BLOCKS 37
#define EH_BLOCKS ((EE + 255) / 256)

__global__ __launch_bounds__(256) void prep_kernel(
    const float* __restrict__ ea,
    const float* __restrict__ nn0_w1, const float* __restrict__ nn0_b1,
    const float* __restrict__ nn0_w2, const float* __restrict__ nn0_b2,
    const float* __restrict__ nn1_w1, const float* __restrict__ nn1_b1,
    const float* __restrict__ nn1_w2, const float* __restrict__ nn1_b2,
    const float* __restrict__ root0, const float* __restrict__ root1,
    const float* __restrict__ root2)
{
    int tid = threadIdx.x;
    int b = blockIdx.x;

    if (b < TR_BLOCKS) {
        __shared__ float ts[64 * 65];
        const float* src;
        float* dst;
        int D;
        if (b < 17)       { D = 32; src = (b < 16) ? nn0_w2 + b * 2048 : nn0_b2;
                            dst = g_WT0 + b * 64 * 32; }
        else if (b == 17) { D = 32; src = root0; dst = g_RT0; }
        else if (b < 35)  { int bb = b - 18; D = 64;
                            src = (bb < 16) ? nn1_w2 + bb * 4096 : nn1_b2;
                            dst = g_WT1 + bb * 64 * 64; }
        else if (b == 35) { D = 64; src = root1; dst = g_RT1; }
        else              { D = 64; src = root2; dst = g_RT2; }

        for (int idx = tid; idx < 64 * D; idx += 256) {
            int o = idx & 63, i = idx >> 6;
            ts[o * 65 + i] = src[i * 64 + o];
        }
        __syncthreads();
        for (int idx = tid; idx < 64 * D; idx += 256) {
            int i = idx & (D - 1), o = idx / D;
            dst[idx] = ts[o * 65 + i];
        }
        return;
    }

    __shared__ float sw0[FEDGE * HID], sw1[FEDGE * HID];
    __shared__ float sb0[HID], sb1[HID];
    if (tid < FEDGE * HID) { sw0[tid] = nn0_w1[tid]; sw1[tid] = nn1_w1[tid]; }
    if (tid < HID)         { sb0[tid] = nn0_b1[tid]; sb1[tid] = nn1_b1[tid]; }
    __syncthreads();

    int e = (b - TR_BLOCKS) * 256 + tid;
    if (e >= EE) return;
    const float4* p = reinterpret_cast<const float4*>(ea + (size_t)e * FEDGE);
    float4 v0 = p[0], v1 = p[1];
    float a[8] = {v0.x, v0.y, v0.z, v0.w, v1.x, v1.y, v1.z, v1.w};
#pragma unroll
    for (int h = 0; h < HID; h++) {
        float s0 = sb0[h], s1 = sb1[h];
#pragma unroll
        for (int j = 0; j < FEDGE; j++) {
            s0 += a[j] * sw0[j * HID + h];
            s1 += a[j] * sw1[j * HID + h];
        }
        g_h0[e * HID + h] = fmaxf(s0, 0.f);
        g_h1[e * HID + h] = fmaxf(s1, 0.f);
    }
}

// ---------------- fused HMMA GEMM (R12 structure + PDL) --------------------
// A = [x | relu(agg+bias)] (128 rows), B = WT^T, 2 column tiles per block.
// Tiles 0..16 -> g_PQ, tile 17 (root product) -> NEXT conv's agg init.
// PDL: MODE>=1 hoists sbias + B-tile-0 staging (prep data, safe) before
// griddepcontrol.wait; only the agg-reading A-stage needs the parent done.
template <int D, int MODE>
__global__ __launch_bounds__(256, 3) void gemm_fused_kernel(
    const float* __restrict__ xin, const float* __restrict__ biasin)
{
    const int SD = D + 8;
    const int CPT = D / 8;
    extern __shared__ ushort smu[];
    ushort* Ah = smu;
    ushort* Al = Ah + 128 * SD;
    ushort* Bh = Al + 128 * SD;
    ushort* Bl = Bh + 64 * SD;
    __shared__ float sbias[64];

    const float* __restrict__ aggin = (MODE == 1) ? g_agg0 : g_agg1;
    float* __restrict__ aggout = (MODE == 0) ? g_agg0 : (MODE == 1 ? g_agg1 : g_agg2);
    const float* __restrict__ WT = (MODE == 0) ? g_WT0 : g_WT1;
    const float* __restrict__ RT = (MODE == 0) ? g_RT0 : (MODE == 1 ? g_RT1 : g_RT2);

    int tid = threadIdx.x, wid = tid >> 5, l = tid & 31;
    int wm = wid & 3, wn = wid >> 2;
    int m0 = blockIdx.y * 128;
    int t0 = blockIdx.x * 2;

    auto stageB = [&](int ct) {
        const float* __restrict__ bsrc = (ct == 17) ? RT : WT + (size_t)ct * 64 * D;
        for (int idx = tid; idx < 64 * CPT; idx += 256) {
            int r = idx / CPT, cb = (idx % CPT) * 8;
            float4 b0 = *reinterpret_cast<const float4*>(bsrc + r * D + cb);
            float4 b1 = *reinterpret_cast<const float4*>(bsrc + r * D + cb + 4);
            float bv[8] = {b0.x,b0.y,b0.z,b0.w,b1.x,b1.y,b1.z,b1.w};
            uint32_t* bh32 = reinterpret_cast<uint32_t*>(Bh);
            uint32_t* bl32 = reinterpret_cast<uint32_t*>(Bl);
            int base = (r * SD + cb) >> 1;
#pragma unroll
            for (int j = 0; j < 4; j++) {
                uint32_t hi, lo;
                split_pack(bv[2*j], bv[2*j+1], hi, lo);
                bh32[base + j] = hi;
                bl32[base + j] = lo;
            }
        }
    };

    if (MODE) {
        // pre-wait prologue: prep outputs only (complete before parent ran)
        if (tid < 64) sbias[tid] = biasin[tid];
        stageB(t0);
        GDC_WAIT();
        GDC_LAUNCH();
        __syncthreads();          // sbias + B0 visible before A-stage reads sbias
    } else {
        GDC_WAIT();
        GDC_LAUNCH();
    }

    // ---- stage A once (full D), fp32 -> bf16 hi/lo ----
    for (int idx = tid; idx < 128 * CPT; idx += 256) {
        int r = idx / CPT, cb = (idx % CPT) * 8;
        int n = m0 + r;
        bool v = (n < NN);
        float vals[8];
        if (MODE == 0) {
            float4 a0 = make_float4(0.f, 0.f, 0.f, 0.f), a1 = a0;
            if (v) {
                a0 = *reinterpret_cast<const float4*>(xin + (size_t)n * D + cb);
                a1 = *reinterpret_cast<const float4*>(xin + (size_t)n * D + cb + 4);
            }
            vals[0]=a0.x; vals[1]=a0.y; vals[2]=a0.z; vals[3]=a0.w;
            vals[4]=a1.x; vals[5]=a1.y; vals[6]=a1.z; vals[7]=a1.w;
        } else {
            float4 g0 = make_float4(0.f,0.f,0.f,0.f), g1 = g0;
            if (v) {
                g0 = *reinterpret_cast<const float4*>(aggin + (size_t)n * EMB + cb);
                g1 = *reinterpret_cast<const float4*>(aggin + (size_t)n * EMB + cb + 4);
            }
            vals[0] = fmaxf(g0.x + sbias[cb+0], 0.f);
            vals[1] = fmaxf(g0.y + sbias[cb+1], 0.f);
            vals[2] = fmaxf(g0.z + sbias[cb+2], 0.f);
            vals[3] = fmaxf(g0.w + sbias[cb+3], 0.f);
            vals[4] = fmaxf(g1.x + sbias[cb+4], 0.f);
            vals[5] = fmaxf(g1.y + sbias[cb+5], 0.f);
            vals[6] = fmaxf(g1.z + sbias[cb+6], 0.f);
            vals[7] = fmaxf(g1.w + sbias[cb+7], 0.f);
        }
        uint32_t* ah32 = reinterpret_cast<uint32_t*>(Ah);
        uint32_t* al32 = reinterpret_cast<uint32_t*>(Al);
        int base = (r * SD + cb) >> 1;
#pragma unroll
        for (int j = 0; j < 4; j++) {
            uint32_t hi, lo;
            split_pack(vals[2*j], vals[2*j+1], hi, lo);
            ah32[base + j] = hi;
            al32[base + j] = lo;
        }
    }

    uint32_t aAh = smem_u32(Ah), aAl = smem_u32(Al);
    uint32_t aBh = smem_u32(Bh), aBl = smem_u32(Bl);

#pragma unroll
    for (int ti = 0; ti < 2; ti++) {
        int ct = t0 + ti;
        if (!(MODE && ti == 0)) stageB(ct);   // B0 already staged pre-wait for MODE>=1
        __syncthreads();   // covers A-stage (+ B-stage this iter)

        float acc[2][4][4];
#pragma unroll
        for (int mi = 0; mi < 2; mi++)
#pragma unroll
            for (int nf = 0; nf < 4; nf++)
#pragma unroll
                for (int q = 0; q < 4; q++) acc[mi][nf][q] = 0.f;

#pragma unroll
        for (int ks = 0; ks < D; ks += 16) {
            uint32_t ahf[2][4], alf[2][4];
#pragma unroll
            for (int mi = 0; mi < 2; mi++) {
                uint32_t off = ((uint32_t)(wm * 32 + mi * 16 + (l & 15)) * SD
                                + ks + (l >> 4) * 8) * 2;
                ldmx4(ahf[mi], aAh + off);
                ldmx4(alf[mi], aAl + off);
            }
            uint32_t bhf[8], blf[8];
#pragma unroll
            for (int g = 0; g < 2; g++) {
                uint32_t off = ((uint32_t)(wn * 32 + g * 16 + (l & 7) + ((l >> 4) & 1) * 8) * SD
                                + ks + ((l >> 3) & 1) * 8) * 2;
                ldmx4(bhf + g * 4, aBh + off);
                ldmx4(blf + g * 4, aBl + off);
            }
#pragma unroll
            for (int mi = 0; mi < 2; mi++)
#pragma unroll
                for (int nf = 0; nf < 4; nf++) {
                    mma_bf16(acc[mi][nf], ahf[mi], bhf[nf*2], bhf[nf*2+1]);
                    mma_bf16(acc[mi][nf], alf[mi], bhf[nf*2], bhf[nf*2+1]);
                    mma_bf16(acc[mi][nf], ahf[mi], blf[nf*2], blf[nf*2+1]);
                }
        }

        // ---- writeback: P,Q tiles -> g_PQ ; root tile -> next agg init ----
#pragma unroll
        for (int mi = 0; mi < 2; mi++)
#pragma unroll
            for (int nf = 0; nf < 4; nf++) {
                int gr = m0 + wm * 32 + mi * 16 + (l >> 2);
                int co = ct * 64 + wn * 32 + nf * 8 + 2 * (l & 3);
                float2 v0 = make_float2(acc[mi][nf][0], acc[mi][nf][1]);
                float2 v1 = make_float2(acc[mi][nf][2], acc[mi][nf][3]);
                if (ct < 17) {
                    if (gr < NN)
                        *reinterpret_cast<float2*>(g_PQ + (size_t)gr * NCOL + co) = v0;
                    if (gr + 8 < NN)
                        *reinterpret_cast<float2*>(g_PQ + (size_t)(gr + 8) * NCOL + co) = v1;
                } else {
                    int cr = co - NCOL;
                    if (gr < NN)
                        *reinterpret_cast<float2*>(aggout + (size_t)gr * EMB + cr) = v0;
                    if (gr + 8 < NN)
                        *reinterpret_cast<float2*>(aggout + (size_t)(gr + 8) * EMB + cr) = v1;
                }
            }
        __syncthreads();
    }
}

// ---------------- per-edge message + scatter (2 edges/warp, vec, PDL) ------
__global__ __launch_bounds__(256) void edge_msg_kernel(const int* __restrict__ ei, int conv)
{
    int gw   = (blockIdx.x * 256 + threadIdx.x) >> 5;
    int lane = threadIdx.x & 31;
    int e    = gw * 2 + (lane >> 4);
    int sub  = lane & 15;

    const float* __restrict__ hsrc = conv ? g_h1 : g_h0;
    float* __restrict__ agg = (conv == 0) ? g_agg0 : (conv == 1 ? g_agg1 : g_agg2);

    // pre-wait prologue: edge index + h loads (inputs / prep output)
    bool act = (e < EE);
    int src = 0, dst = 0;
    float hv = 0.f;
    if (act) {
        src = ei[e];
        dst = ei[EE + e];
        hv  = hsrc[(size_t)e * HID + sub];
    }
    GDC_WAIT();
    GDC_LAUNCH();
    if (!act) return;

    const float* __restrict__ P = g_PQ + (size_t)src * NCOL;
    float4 acc = *reinterpret_cast<const float4*>(P + QOFF + sub * 4);
#pragma unroll
    for (int h = 0; h < HID; h++) {
        float w = __shfl_sync(0xffffffffu, hv, (lane & 16) | h);
        float4 f = *reinterpret_cast<const float4*>(P + h * EMB + sub * 4);
        acc.x += w * f.x; acc.y += w * f.y; acc.z += w * f.z; acc.w += w * f.w;
    }
    float* a = agg + (size_t)dst * EMB + sub * 4;
    asm volatile("red.global.add.v4.f32 [%0], {%1,%2,%3,%4};"
                 :: "l"(a), "f"(acc.x), "f"(acc.y), "f"(acc.z), "f"(acc.w)
                 : "memory");
}

// ---------------- pool (fused final combine; batch sorted, x >= 0) --------
__global__ __launch_bounds__(256) void pool_kernel(const int* __restrict__ batch,
                                                   const float* __restrict__ bias2)
{
    int tid = threadIdx.x;
    int o = tid & 63, seg = tid >> 6;
    int n0 = blockIdx.x * 32 + seg * 8;
    float bz = __ldg(bias2 + o);
    GDC_WAIT();
    GDC_LAUNCH();
    int curb = -1;
    float m = 0.f;
    for (int k = 0; k < 8; k++) {
        int n = n0 + k;
        if (n >= NN) break;
        int b = batch[n];
        if (b != curb) {
            if (curb >= 0)
                atomicMax(reinterpret_cast<unsigned*>(g_pool + (size_t)curb * EMB + o),
                          __float_as_uint(m));
            curb = b;
            m = 0.f;
        }
        float x = fmaxf(g_agg2[(size_t)n * EMB + o] + bz, 0.f);
        m = fmaxf(m, x);
    }
    if (curb >= 0)
        atomicMax(reinterpret_cast<unsigned*>(g_pool + (size_t)curb * EMB + o),
                  __float_as_uint(m));
}

// ---------------- head -----------------------------------------------------
__global__ __launch_bounds__(64) void head_kernel(
    const float* __restrict__ lin0w, const float* __restrict__ lin0b,
    const float* __restrict__ lin1w, const float* __restrict__ lin1b,
    float* __restrict__ out)
{
    __shared__ float pg[EMB];
    __shared__ float red[EMB];
    int g = blockIdx.x, o = threadIdx.x;
    float bo = lin0b[o];          // pre-wait: inputs only
    float w1 = lin1w[o];
    GDC_WAIT();
    pg[o] = g_pool[(size_t)g * EMB + o];
    __syncthreads();

    float h = bo;
#pragma unroll
    for (int i = 0; i < EMB; i++) h += pg[i] * lin0w[i * EMB + o];
    red[o] = h * w1;
    __syncthreads();
#pragma unroll
    for (int s = 32; s > 0; s >>= 1) {
        if (o < s) red[o] += red[o + s];
        __syncthreads();
    }
    if (o == 0) out[g] = red[0] + lin1b[0];
}

// ---------------- PDL launch helper ----------------------------------------
template <typename... Args>
static void launch_pdl(void (*func)(Args...), dim3 grid, dim3 block,
                       size_t smem, Args... args)
{
    cudaLaunchConfig_t cfg = {};
    cfg.gridDim = grid;
    cfg.blockDim = block;
    cfg.dynamicSmemBytes = smem;
    cfg.stream = 0;
    cudaLaunchAttribute attr[1];
    attr[0].id = cudaLaunchAttributeProgrammaticStreamSerialization;
    attr[0].val.programmaticStreamSerializationAllowed = 1;
    cfg.attrs = attr;
    cfg.numAttrs = 1;
    cudaLaunchKernelEx(&cfg, func, args...);
}

// ---------------- launch ----------------------------------------------------
extern "C" void kernel_launch(void* const* d_in, const int* in_sizes, int n_in,
                              void* d_out, int out_size)
{
    const float* x_p    = (const float*)d_in[0];
    const float* ea     = (const float*)d_in[2];
    const int*   ei     = (const int*)  d_in[4];
    const int*   batch  = (const int*)  d_in[5];
    const float* nn0_w1 = (const float*)d_in[6];
    const float* nn0_b1 = (const float*)d_in[7];
    const float* nn0_w2 = (const float*)d_in[8];
    const float* nn0_b2 = (const float*)d_in[9];
    const float* nn1_w1 = (const float*)d_in[10];
    const float* nn1_b1 = (const float*)d_in[11];
    const float* nn1_w2 = (const float*)d_in[12];
    const float* nn1_b2 = (const float*)d_in[13];
    const float* root0  = (const float*)d_in[14];
    const float* bias0  = (const float*)d_in[15];
    const float* root1  = (const float*)d_in[16];
    const float* bias1  = (const float*)d_in[17];
    const float* root2  = (const float*)d_in[18];
    const float* bias2  = (const float*)d_in[19];
    const float* lin0_w = (const float*)d_in[20];
    const float* lin0_b = (const float*)d_in[21];
    const float* lin1_w = (const float*)d_in[22];
    const float* lin1_b = (const float*)d_in[23];
    float* out = (float*)d_out;

    size_t smem32 = 128 * 40 * 4 + 64 * 40 * 4;   // 30720
    size_t smem64 = 128 * 72 * 4 + 64 * 72 * 4;   // 55296

    static bool attr_done = false;
    if (!attr_done) {
        cudaFuncSetAttribute(gemm_fused_kernel<64, 1>,
                             cudaFuncAttributeMaxDynamicSharedMemorySize, (int)smem64);
        cudaFuncSetAttribute(gemm_fused_kernel<64, 2>,
                             cudaFuncAttributeMaxDynamicSharedMemorySize, (int)smem64);
        attr_done = true;
    }

    dim3 gemm_grid(9, (NN + 127) / 128);
    int msg_blocks = EE / 16;

    prep_kernel<<<TR_BLOCKS + EH_BLOCKS, 256>>>(
        ea, nn0_w1, nn0_b1, nn0_w2, nn0_b2, nn1_w1, nn1_b1, nn1_w2, nn1_b2,
        root0, root1, root2);

    // ---- conv0 ----
    launch_pdl(gemm_fused_kernel<32, 0>, gemm_grid, dim3(256), smem32, x_p, bias0);
    launch_pdl(edge_msg_kernel, dim3(msg_blocks), dim3(256), (size_t)0, ei, 0);

    // ---- conv1 ----
    launch_pdl(gemm_fused_kernel<64, 1>, gemm_grid, dim3(256), smem64,
               (const float*)nullptr, bias0);
    launch_pdl(edge_msg_kernel, dim3(msg_blocks), dim3(256), (size_t)0, ei, 1);

    // ---- conv2 ----
    launch_pdl(gemm_fused_kernel<64, 2>, gemm_grid, dim3(256), smem64,
               (const float*)nullptr, bias1);
    launch_pdl(edge_msg_kernel, dim3(msg_blocks), dim3(256), (size_t)0, ei, 2);

    // ---- pool (fused final combine) + head ----
    launch_pdl(pool_kernel, dim3((NN + 31) / 32), dim3(256), (size_t)0, batch, bias2);
    launch_pdl(head_kernel, dim3(NG), dim3(64), (size_t)0,
               lin0_w, lin0_b, lin1_w, lin1_b, out);
}

// round 14
// speedup vs baseline: 1.6370x; 1.1308x over previous
#include <cuda_runtime.h>
#include <cuda_fp16.h>
#include <cstdint>

#define NN      10000
#define EE      30000
#define FEDGE   8
#define EMB     64
#define HID     16
#define NG      64
#define NCOL    1088   // 1024 P | 64 Q
#define QOFF    1024

// PDL: programmatic dependent launch (sm_90+ base PTX, graph-capturable)
#define GDC_WAIT()   asm volatile("griddepcontrol.wait;" ::: "memory")
#define GDC_LAUNCH() asm volatile("griddepcontrol.launch_dependents;" ::: "memory")

// ---------------- scratch (device globals) --------------------------------
__device__ __align__(128) float g_h0[EE * HID];
__device__ __align__(128) float g_h1[EE * HID];
__device__ __align__(128) float g_PQ[(size_t)NN * NCOL];
// agg buffers double as root-product init: gemm tile-17 writes x@root into
// the NEXT conv's agg, edge_msg accumulates messages on top.
__device__ __align__(128) float g_agg0[NN * EMB];
__device__ __align__(128) float g_agg1[NN * EMB];
__device__ __align__(128) float g_agg2[NN * EMB];
__device__ __align__(128) float g_WT0[NCOL * 32];  // [c][i] P+Q, conv0
__device__ __align__(128) float g_WT1[NCOL * 64];  // [c][i] P+Q, convs 1&2
__device__ __align__(128) float g_RT0[64 * 32];    // [o][i] rootT
__device__ __align__(128) float g_RT1[64 * 64];
__device__ __align__(128) float g_RT2[64 * 64];
__device__ __align__(128) float g_pool[NG * EMB];

// ---------------- helpers --------------------------------------------------
__device__ __forceinline__ uint32_t smem_u32(const void* p) {
    uint32_t a;
    asm("{ .reg .u64 t; cvta.to.shared.u64 t, %1; cvt.u32.u64 %0, t; }" : "=r"(a) : "l"(p));
    return a;
}
__device__ __forceinline__ void ldmx4(uint32_t* r, uint32_t addr) {
    asm volatile("ldmatrix.sync.aligned.m8n8.x4.shared.b16 {%0,%1,%2,%3}, [%4];"
        : "=r"(r[0]), "=r"(r[1]), "=r"(r[2]), "=r"(r[3]) : "r"(addr));
}
__device__ __forceinline__ void mma_fp16(float* d, const uint32_t* a,
                                         uint32_t b0, uint32_t b1) {
    asm volatile("mma.sync.aligned.m16n8k16.row.col.f32.f16.f16.f32 "
        "{%0,%1,%2,%3}, {%4,%5,%6,%7}, {%8,%9}, {%0,%1,%2,%3};"
        : "+f"(d[0]), "+f"(d[1]), "+f"(d[2]), "+f"(d[3])
        : "r"(a[0]), "r"(a[1]), "r"(a[2]), "r"(a[3]), "r"(b0), "r"(b1));
}
// pack two fp32 -> packed fp16x2 (round-to-nearest)
__device__ __forceinline__ uint32_t pack_h2(float x, float y) {
    __half2 h = __floats2half2_rn(x, y);
    return *reinterpret_cast<uint32_t*>(&h);
}
// fp16 hi/lo split of a fp32 pair
__device__ __forceinline__ void split_h2(float x, float y,
                                         uint32_t& hi, uint32_t& lo) {
    __half hx = __float2half_rn(x), hy = __float2half_rn(y);
    __half lx = __float2half_rn(x - __half2float(hx));
    __half ly = __float2half_rn(y - __half2float(hy));
    hi = ((uint32_t)__half_as_ushort(hy) << 16) | __half_as_ushort(hx);
    lo = ((uint32_t)__half_as_ushort(ly) << 16) | __half_as_ushort(lx);
}

// ---------------- prep: transposes + edge MLP hiddens ----------------------
#define TR_BLOCKS 37
#define EH_BLOCKS ((EE + 255) / 256)

__global__ __launch_bounds__(256) void prep_kernel(
    const float* __restrict__ ea,
    const float* __restrict__ nn0_w1, const float* __restrict__ nn0_b1,
    const float* __restrict__ nn0_w2, const float* __restrict__ nn0_b2,
    const float* __restrict__ nn1_w1, const float* __restrict__ nn1_b1,
    const float* __restrict__ nn1_w2, const float* __restrict__ nn1_b2,
    const float* __restrict__ root0, const float* __restrict__ root1,
    const float* __restrict__ root2)
{
    int tid = threadIdx.x;
    int b = blockIdx.x;

    if (b < TR_BLOCKS) {
        __shared__ float ts[64 * 65];
        const float* src;
        float* dst;
        int D;
        if (b < 17)       { D = 32; src = (b < 16) ? nn0_w2 + b * 2048 : nn0_b2;
                            dst = g_WT0 + b * 64 * 32; }
        else if (b == 17) { D = 32; src = root0; dst = g_RT0; }
        else if (b < 35)  { int bb = b - 18; D = 64;
                            src = (bb < 16) ? nn1_w2 + bb * 4096 : nn1_b2;
                            dst = g_WT1 + bb * 64 * 64; }
        else if (b == 35) { D = 64; src = root1; dst = g_RT1; }
        else              { D = 64; src = root2; dst = g_RT2; }

        for (int idx = tid; idx < 64 * D; idx += 256) {
            int o = idx & 63, i = idx >> 6;
            ts[o * 65 + i] = src[i * 64 + o];
        }
        __syncthreads();
        for (int idx = tid; idx < 64 * D; idx += 256) {
            int i = idx & (D - 1), o = idx / D;
            dst[idx] = ts[o * 65 + i];
        }
        return;
    }

    __shared__ float sw0[FEDGE * HID], sw1[FEDGE * HID];
    __shared__ float sb0[HID], sb1[HID];
    if (tid < FEDGE * HID) { sw0[tid] = nn0_w1[tid]; sw1[tid] = nn1_w1[tid]; }
    if (tid < HID)         { sb0[tid] = nn0_b1[tid]; sb1[tid] = nn1_b1[tid]; }
    __syncthreads();

    int e = (b - TR_BLOCKS) * 256 + tid;
    if (e >= EE) return;
    const float4* p = reinterpret_cast<const float4*>(ea + (size_t)e * FEDGE);
    float4 v0 = p[0], v1 = p[1];
    float a[8] = {v0.x, v0.y, v0.z, v0.w, v1.x, v1.y, v1.z, v1.w};
#pragma unroll
    for (int h = 0; h < HID; h++) {
        float s0 = sb0[h], s1 = sb1[h];
#pragma unroll
        for (int j = 0; j < FEDGE; j++) {
            s0 += a[j] * sw0[j * HID + h];
            s1 += a[j] * sw1[j * HID + h];
        }
        g_h0[e * HID + h] = fmaxf(s0, 0.f);
        g_h1[e * HID + h] = fmaxf(s1, 0.f);
    }
}

// ---------------- fused HMMA GEMM (fp16: A hi-only, B hi/lo, 2 products) ---
// A = [x | relu(agg+bias)] (128 rows), B = WT^T, 2 column tiles per block.
// Tiles 0..16 -> g_PQ, tile 17 (root product) -> NEXT conv's agg init.
// Precision: fp16 A (11-bit mantissa, residual 2^-11 dropped), B split
// hi/lo -> C = Ah*Bh + Ah*Bl. Error ~1e-4 class, under the 1e-3 gate.
template <int D, int MODE>
__global__ __launch_bounds__(256, 3) void gemm_fused_kernel(
    const float* __restrict__ xin, const float* __restrict__ biasin)
{
    const int SD = D + 8;
    const int CPT = D / 8;
    extern __shared__ ushort smu[];
    ushort* Ah = smu;                    // 128*SD (hi only)
    ushort* Bh = Ah + 128 * SD;          // 64*SD
    ushort* Bl = Bh + 64 * SD;           // 64*SD
    __shared__ float sbias[64];

    const float* __restrict__ aggin = (MODE == 1) ? g_agg0 : g_agg1;
    float* __restrict__ aggout = (MODE == 0) ? g_agg0 : (MODE == 1 ? g_agg1 : g_agg2);
    const float* __restrict__ WT = (MODE == 0) ? g_WT0 : g_WT1;
    const float* __restrict__ RT = (MODE == 0) ? g_RT0 : (MODE == 1 ? g_RT1 : g_RT2);

    int tid = threadIdx.x, wid = tid >> 5, l = tid & 31;
    int wm = wid & 3, wn = wid >> 2;
    int m0 = blockIdx.y * 128;
    int t0 = blockIdx.x * 2;

    auto stageB = [&](int ct) {
        const float* __restrict__ bsrc = (ct == 17) ? RT : WT + (size_t)ct * 64 * D;
        for (int idx = tid; idx < 64 * CPT; idx += 256) {
            int r = idx / CPT, cb = (idx % CPT) * 8;
            float4 b0 = *reinterpret_cast<const float4*>(bsrc + r * D + cb);
            float4 b1 = *reinterpret_cast<const float4*>(bsrc + r * D + cb + 4);
            float bv[8] = {b0.x,b0.y,b0.z,b0.w,b1.x,b1.y,b1.z,b1.w};
            uint32_t* bh32 = reinterpret_cast<uint32_t*>(Bh);
            uint32_t* bl32 = reinterpret_cast<uint32_t*>(Bl);
            int base = (r * SD + cb) >> 1;
#pragma unroll
            for (int j = 0; j < 4; j++) {
                uint32_t hi, lo;
                split_h2(bv[2*j], bv[2*j+1], hi, lo);
                bh32[base + j] = hi;
                bl32[base + j] = lo;
            }
        }
    };

    if (MODE) {
        // pre-wait prologue: prep outputs only (complete before parent ran)
        if (tid < 64) sbias[tid] = biasin[tid];
        stageB(t0);
        GDC_WAIT();
        GDC_LAUNCH();
        __syncthreads();          // sbias + B0 visible before A-stage reads sbias
    } else {
        GDC_WAIT();
        GDC_LAUNCH();
    }

    // ---- stage A once (full D), fp32 -> fp16 hi only ----
    for (int idx = tid; idx < 128 * CPT; idx += 256) {
        int r = idx / CPT, cb = (idx % CPT) * 8;
        int n = m0 + r;
        bool v = (n < NN);
        float vals[8];
        if (MODE == 0) {
            float4 a0 = make_float4(0.f, 0.f, 0.f, 0.f), a1 = a0;
            if (v) {
                a0 = *reinterpret_cast<const float4*>(xin + (size_t)n * D + cb);
                a1 = *reinterpret_cast<const float4*>(xin + (size_t)n * D + cb + 4);
            }
            vals[0]=a0.x; vals[1]=a0.y; vals[2]=a0.z; vals[3]=a0.w;
            vals[4]=a1.x; vals[5]=a1.y; vals[6]=a1.z; vals[7]=a1.w;
        } else {
            float4 g0 = make_float4(0.f,0.f,0.f,0.f), g1 = g0;
            if (v) {
                g0 = *reinterpret_cast<const float4*>(aggin + (size_t)n * EMB + cb);
                g1 = *reinterpret_cast<const float4*>(aggin + (size_t)n * EMB + cb + 4);
            }
            vals[0] = fmaxf(g0.x + sbias[cb+0], 0.f);
            vals[1] = fmaxf(g0.y + sbias[cb+1], 0.f);
            vals[2] = fmaxf(g0.z + sbias[cb+2], 0.f);
            vals[3] = fmaxf(g0.w + sbias[cb+3], 0.f);
            vals[4] = fmaxf(g1.x + sbias[cb+4], 0.f);
            vals[5] = fmaxf(g1.y + sbias[cb+5], 0.f);
            vals[6] = fmaxf(g1.z + sbias[cb+6], 0.f);
            vals[7] = fmaxf(g1.w + sbias[cb+7], 0.f);
        }
        uint32_t* ah32 = reinterpret_cast<uint32_t*>(Ah);
        int base = (r * SD + cb) >> 1;
#pragma unroll
        for (int j = 0; j < 4; j++)
            ah32[base + j] = pack_h2(vals[2*j], vals[2*j+1]);
    }

    uint32_t aAh = smem_u32(Ah);
    uint32_t aBh = smem_u32(Bh), aBl = smem_u32(Bl);

#pragma unroll
    for (int ti = 0; ti < 2; ti++) {
        int ct = t0 + ti;
        if (!(MODE && ti == 0)) stageB(ct);   // B0 already staged pre-wait for MODE>=1
        __syncthreads();   // covers A-stage (+ B-stage this iter)

        float acc[2][4][4];
#pragma unroll
        for (int mi = 0; mi < 2; mi++)
#pragma unroll
            for (int nf = 0; nf < 4; nf++)
#pragma unroll
                for (int q = 0; q < 4; q++) acc[mi][nf][q] = 0.f;

#pragma unroll
        for (int ks = 0; ks < D; ks += 16) {
            uint32_t ahf[2][4];
#pragma unroll
            for (int mi = 0; mi < 2; mi++) {
                uint32_t off = ((uint32_t)(wm * 32 + mi * 16 + (l & 15)) * SD
                                + ks + (l >> 4) * 8) * 2;
                ldmx4(ahf[mi], aAh + off);
            }
            uint32_t bhf[8], blf[8];
#pragma unroll
            for (int g = 0; g < 2; g++) {
                uint32_t off = ((uint32_t)(wn * 32 + g * 16 + (l & 7) + ((l >> 4) & 1) * 8) * SD
                                + ks + ((l >> 3) & 1) * 8) * 2;
                ldmx4(bhf + g * 4, aBh + off);
                ldmx4(blf + g * 4, aBl + off);
            }
#pragma unroll
            for (int mi = 0; mi < 2; mi++)
#pragma unroll
                for (int nf = 0; nf < 4; nf++) {
                    mma_fp16(acc[mi][nf], ahf[mi], bhf[nf*2], bhf[nf*2+1]);
                    mma_fp16(acc[mi][nf], ahf[mi], blf[nf*2], blf[nf*2+1]);
                }
        }

        // ---- writeback: P,Q tiles -> g_PQ ; root tile -> next agg init ----
#pragma unroll
        for (int mi = 0; mi < 2; mi++)
#pragma unroll
            for (int nf = 0; nf < 4; nf++) {
                int gr = m0 + wm * 32 + mi * 16 + (l >> 2);
                int co = ct * 64 + wn * 32 + nf * 8 + 2 * (l & 3);
                float2 v0 = make_float2(acc[mi][nf][0], acc[mi][nf][1]);
                float2 v1 = make_float2(acc[mi][nf][2], acc[mi][nf][3]);
                if (ct < 17) {
                    if (gr < NN)
                        *reinterpret_cast<float2*>(g_PQ + (size_t)gr * NCOL + co) = v0;
                    if (gr + 8 < NN)
                        *reinterpret_cast<float2*>(g_PQ + (size_t)(gr + 8) * NCOL + co) = v1;
                } else {
                    int cr = co - NCOL;
                    if (gr < NN)
                        *reinterpret_cast<float2*>(aggout + (size_t)gr * EMB + cr) = v0;
                    if (gr + 8 < NN)
                        *reinterpret_cast<float2*>(aggout + (size_t)(gr + 8) * EMB + cr) = v1;
                }
            }
        __syncthreads();
    }
}

// ---------------- per-edge message + scatter (2 edges/warp, vec, PDL) ------
__global__ __launch_bounds__(256) void edge_msg_kernel(const int* __restrict__ ei, int conv)
{
    int gw   = (blockIdx.x * 256 + threadIdx.x) >> 5;
    int lane = threadIdx.x & 31;
    int e    = gw * 2 + (lane >> 4);
    int sub  = lane & 15;

    const float* __restrict__ hsrc = conv ? g_h1 : g_h0;
    float* __restrict__ agg = (conv == 0) ? g_agg0 : (conv == 1 ? g_agg1 : g_agg2);

    // pre-wait prologue: edge index + h loads (inputs / prep output)
    bool act = (e < EE);
    int src = 0, dst = 0;
    float hv = 0.f;
    if (act) {
        src = ei[e];
        dst = ei[EE + e];
        hv  = hsrc[(size_t)e * HID + sub];
    }
    GDC_WAIT();
    GDC_LAUNCH();
    if (!act) return;

    const float* __restrict__ P = g_PQ + (size_t)src * NCOL;
    float4 acc = *reinterpret_cast<const float4*>(P + QOFF + sub * 4);
#pragma unroll
    for (int h = 0; h < HID; h++) {
        float w = __shfl_sync(0xffffffffu, hv, (lane & 16) | h);
        float4 f = *reinterpret_cast<const float4*>(P + h * EMB + sub * 4);
        acc.x += w * f.x; acc.y += w * f.y; acc.z += w * f.z; acc.w += w * f.w;
    }
    float* a = agg + (size_t)dst * EMB + sub * 4;
    asm volatile("red.global.add.v4.f32 [%0], {%1,%2,%3,%4};"
                 :: "l"(a), "f"(acc.x), "f"(acc.y), "f"(acc.z), "f"(acc.w)
                 : "memory");
}

// ---------------- pool (fused final combine; batch sorted, x >= 0) --------
__global__ __launch_bounds__(256) void pool_kernel(const int* __restrict__ batch,
                                                   const float* __restrict__ bias2)
{
    int tid = threadIdx.x;
    int o = tid & 63, seg = tid >> 6;
    int n0 = blockIdx.x * 32 + seg * 8;
    float bz = __ldg(bias2 + o);
    GDC_WAIT();
    GDC_LAUNCH();
    int curb = -1;
    float m = 0.f;
    for (int k = 0; k < 8; k++) {
        int n = n0 + k;
        if (n >= NN) break;
        int b = batch[n];
        if (b != curb) {
            if (curb >= 0)
                atomicMax(reinterpret_cast<unsigned*>(g_pool + (size_t)curb * EMB + o),
                          __float_as_uint(m));
            curb = b;
            m = 0.f;
        }
        float x = fmaxf(g_agg2[(size_t)n * EMB + o] + bz, 0.f);
        m = fmaxf(m, x);
    }
    if (curb >= 0)
        atomicMax(reinterpret_cast<unsigned*>(g_pool + (size_t)curb * EMB + o),
                  __float_as_uint(m));
}

// ---------------- head -----------------------------------------------------
__global__ __launch_bounds__(64) void head_kernel(
    const float* __restrict__ lin0w, const float* __restrict__ lin0b,
    const float* __restrict__ lin1w, const float* __restrict__ lin1b,
    float* __restrict__ out)
{
    __shared__ float pg[EMB];
    __shared__ float red[EMB];
    int g = blockIdx.x, o = threadIdx.x;
    float bo = lin0b[o];          // pre-wait: inputs only
    float w1 = lin1w[o];
    GDC_WAIT();
    pg[o] = g_pool[(size_t)g * EMB + o];
    __syncthreads();

    float h = bo;
#pragma unroll
    for (int i = 0; i < EMB; i++) h += pg[i] * lin0w[i * EMB + o];
    red[o] = h * w1;
    __syncthreads();
#pragma unroll
    for (int s = 32; s > 0; s >>= 1) {
        if (o < s) red[o] += red[o + s];
        __syncthreads();
    }
    if (o == 0) out[g] = red[0] + lin1b[0];
}

// ---------------- PDL launch helper ----------------------------------------
template <typename... Args>
static void launch_pdl(void (*func)(Args...), dim3 grid, dim3 block,
                       size_t smem, Args... args)
{
    cudaLaunchConfig_t cfg = {};
    cfg.gridDim = grid;
    cfg.blockDim = block;
    cfg.dynamicSmemBytes = smem;
    cfg.stream = 0;
    cudaLaunchAttribute attr[1];
    attr[0].id = cudaLaunchAttributeProgrammaticStreamSerialization;
    attr[0].val.programmaticStreamSerializationAllowed = 1;
    cfg.attrs = attr;
    cfg.numAttrs = 1;
    cudaLaunchKernelEx(&cfg, func, args...);
}

// ---------------- launch ----------------------------------------------------
extern "C" void kernel_launch(void* const* d_in, const int* in_sizes, int n_in,
                              void* d_out, int out_size)
{
    const float* x_p    = (const float*)d_in[0];
    const float* ea     = (const float*)d_in[2];
    const int*   ei     = (const int*)  d_in[4];
    const int*   batch  = (const int*)  d_in[5];
    const float* nn0_w1 = (const float*)d_in[6];
    const float* nn0_b1 = (const float*)d_in[7];
    const float* nn0_w2 = (const float*)d_in[8];
    const float* nn0_b2 = (const float*)d_in[9];
    const float* nn1_w1 = (const float*)d_in[10];
    const float* nn1_b1 = (const float*)d_in[11];
    const float* nn1_w2 = (const float*)d_in[12];
    const float* nn1_b2 = (const float*)d_in[13];
    const float* root0  = (const float*)d_in[14];
    const float* bias0  = (const float*)d_in[15];
    const float* root1  = (const float*)d_in[16];
    const float* bias1  = (const float*)d_in[17];
    const float* root2  = (const float*)d_in[18];
    const float* bias2  = (const float*)d_in[19];
    const float* lin0_w = (const float*)d_in[20];
    const float* lin0_b = (const float*)d_in[21];
    const float* lin1_w = (const float*)d_in[22];
    const float* lin1_b = (const float*)d_in[23];
    float* out = (float*)d_out;

    // smem: A(hi) 128*SD*2 + B(hi+lo) 2*64*SD*2 bytes
    size_t smem32 = 128 * 40 * 2 + 2 * 64 * 40 * 2;   // 20480
    size_t smem64 = 128 * 72 * 2 + 2 * 64 * 72 * 2;   // 36864

    dim3 gemm_grid(9, (NN + 127) / 128);
    int msg_blocks = EE / 16;

    prep_kernel<<<TR_BLOCKS + EH_BLOCKS, 256>>>(
        ea, nn0_w1, nn0_b1, nn0_w2, nn0_b2, nn1_w1, nn1_b1, nn1_w2, nn1_b2,
        root0, root1, root2);

    // ---- conv0 ----
    launch_pdl(gemm_fused_kernel<32, 0>, gemm_grid, dim3(256), smem32, x_p, bias0);
    launch_pdl(edge_msg_kernel, dim3(msg_blocks), dim3(256), (size_t)0, ei, 0);

    // ---- conv1 ----
    launch_pdl(gemm_fused_kernel<64, 1>, gemm_grid, dim3(256), smem64,
               (const float*)nullptr, bias0);
    launch_pdl(edge_msg_kernel, dim3(msg_blocks), dim3(256), (size_t)0, ei, 1);

    // ---- conv2 ----
    launch_pdl(gemm_fused_kernel<64, 2>, gemm_grid, dim3(256), smem64,
               (const float*)nullptr, bias1);
    launch_pdl(edge_msg_kernel, dim3(msg_blocks), dim3(256), (size_t)0, ei, 2);

    // ---- pool (fused final combine) + head ----
    launch_pdl(pool_kernel, dim3((NN + 31) / 32), dim3(256), (size_t)0, batch, bias2);
    launch_pdl(head_kernel, dim3(NG), dim3(64), (size_t)0,
               lin0_w, lin0_b, lin1_w, lin1_b, out);
}